// round 3
// baseline (speedup 1.0000x reference)
#include <cuda_runtime.h>
#include <cstdint>
#include <cstdio>

#define BATCH 64
#define TT    512
#define DIN   512
#define HID   1024
#define G4    4096
#define DDEC  1024

// ---------------- device scratch (static, allocation-free) ----------------
// Xpre[dir][t][b][n] = x[b][t] @ W_ih[dir]^T + b_ih + b_hh   (1 GiB)
__device__ float g_Xpre[2][TT][BATCH][G4];
// h ping-pong: [parity][dir][b][j]
__device__ float g_h[2][2][BATCH][HID];
// cell state (in-place across steps): [dir][b][j]
__device__ float g_c[2][BATCH][HID];

// ---------------- helpers ----------------
__device__ __forceinline__ uint32_t f2tf32(float x) {
    uint32_t r;
    asm("cvt.rna.tf32.f32 %0, %1;" : "=r"(r) : "f"(x));
    return r;
}

__device__ __forceinline__ void mma_tf32(float* c,
                                         uint32_t a0, uint32_t a1, uint32_t a2, uint32_t a3,
                                         uint32_t b0, uint32_t b1) {
    asm volatile(
        "mma.sync.aligned.m16n8k8.row.col.f32.tf32.tf32.f32 "
        "{%0,%1,%2,%3}, {%4,%5,%6,%7}, {%8,%9}, {%0,%1,%2,%3};"
        : "+f"(c[0]), "+f"(c[1]), "+f"(c[2]), "+f"(c[3])
        : "r"(a0), "r"(a1), "r"(a2), "r"(a3), "r"(b0), "r"(b1));
}

__device__ __forceinline__ float sigf(float x) { return 1.0f / (1.0f + expf(-x)); }

// ---------------- init: zero h (parity 0) and c ----------------
__global__ void init_states() {
    int i = blockIdx.x * blockDim.x + threadIdx.x;   // 0 .. 2*64*1024-1
    ((float*)g_h)[i] = 0.0f;   // zeroes g_h[0][*][*][*] (first 131072 floats)
    ((float*)g_c)[i] = 0.0f;
}

// ---------------- big GEMM: Xpre = X @ W_ih^T + (b_ih + b_hh) ----------------
// grid: (64 n-tiles, 512 t, 2 dir), block: 128 threads (4 warps)
// block computes 64 (batch) x 64 (gate cols) for one timestep.
__global__ void __launch_bounds__(128) gemm_xpre(
    const float* __restrict__ X,       // (B, T, DIN)
    const float* __restrict__ Wih_f, const float* __restrict__ Wih_b,   // (4H, DIN)
    const float* __restrict__ bih_f, const float* __restrict__ bhh_f,
    const float* __restrict__ bih_b, const float* __restrict__ bhh_b) {
    const int nt  = blockIdx.x;
    const int t   = blockIdx.y;
    const int dir = blockIdx.z;
    const float* W  = dir ? Wih_b : Wih_f;
    const float* bi = dir ? bih_b : bih_f;
    const float* bh = dir ? bhh_b : bhh_f;
    const int n0 = nt * 64;

    __shared__ uint32_t sA[64][36];
    __shared__ uint32_t sB[64][36];

    const int tid  = threadIdx.x;
    const int warp = tid >> 5;
    const int lane = tid & 31;

    float acc[8][4];
#pragma unroll
    for (int i = 0; i < 8; i++)
#pragma unroll
        for (int e = 0; e < 4; e++) acc[i][e] = 0.0f;

    for (int k0 = 0; k0 < DIN; k0 += 32) {
        // A: rows = batch b (fixed t), X[b][t][k0+c]
        for (int i = tid; i < 512; i += 128) {
            int r = i >> 3, c = (i & 7) * 4;
            float4 v = *(const float4*)&X[((size_t)r * TT + t) * DIN + k0 + c];
            sA[r][c + 0] = f2tf32(v.x);
            sA[r][c + 1] = f2tf32(v.y);
            sA[r][c + 2] = f2tf32(v.z);
            sA[r][c + 3] = f2tf32(v.w);
        }
        // B: rows = W_ih rows n0+r
        for (int i = tid; i < 512; i += 128) {
            int r = i >> 3, c = (i & 7) * 4;
            float4 v = *(const float4*)&W[(size_t)(n0 + r) * DIN + k0 + c];
            sB[r][c + 0] = f2tf32(v.x);
            sB[r][c + 1] = f2tf32(v.y);
            sB[r][c + 2] = f2tf32(v.z);
            sB[r][c + 3] = f2tf32(v.w);
        }
        __syncthreads();
#pragma unroll
        for (int kk = 0; kk < 32; kk += 8) {
            uint32_t a0 = sA[warp * 16 + (lane >> 2)    ][kk + (lane & 3)];
            uint32_t a1 = sA[warp * 16 + (lane >> 2) + 8][kk + (lane & 3)];
            uint32_t a2 = sA[warp * 16 + (lane >> 2)    ][kk + (lane & 3) + 4];
            uint32_t a3 = sA[warp * 16 + (lane >> 2) + 8][kk + (lane & 3) + 4];
#pragma unroll
            for (int nf = 0; nf < 8; nf++) {
                uint32_t b0 = sB[nf * 8 + (lane >> 2)][kk + (lane & 3)];
                uint32_t b1 = sB[nf * 8 + (lane >> 2)][kk + (lane & 3) + 4];
                mma_tf32(acc[nf], a0, a1, a2, a3, b0, b1);
            }
        }
        __syncthreads();
    }

    // epilogue: add bias, write Xpre[dir][t][b][n]
    float* dst = &g_Xpre[dir][t][0][0];
    const int r_lo = warp * 16 + (lane >> 2);
#pragma unroll
    for (int nf = 0; nf < 8; nf++) {
        int c0 = n0 + nf * 8 + (lane & 3) * 2;
        float bias0 = bi[c0] + bh[c0];
        float bias1 = bi[c0 + 1] + bh[c0 + 1];
        dst[(size_t)r_lo * G4 + c0]           = acc[nf][0] + bias0;
        dst[(size_t)r_lo * G4 + c0 + 1]       = acc[nf][1] + bias1;
        dst[(size_t)(r_lo + 8) * G4 + c0]     = acc[nf][2] + bias0;
        dst[(size_t)(r_lo + 8) * G4 + c0 + 1] = acc[nf][3] + bias1;
    }
}

// ---------------- per-timestep fused kernel ----------------
// grid: (64 j-tiles of 16 hidden units, 2 dirs), block 128 threads (4 warps).
// Block computes 64 gate columns {g*1024 + j0+jj : g in 0..3, jj in 0..15},
// GEMM h @ W_hh^T (M=64,K=1024), then the LSTM elementwise update.
__global__ void __launch_bounds__(128) lstm_step(
    const float* __restrict__ Whh_f, const float* __restrict__ Whh_b,   // (4H, H)
    int t, float* __restrict__ out) {
    const int dir = blockIdx.y;
    const int j0  = blockIdx.x * 16;
    const float* Whh = dir ? Whh_b : Whh_f;
    const int par = t & 1;
    const float* hin  = &g_h[par][dir][0][0];
    float*       hout = &g_h[par ^ 1][dir][0][0];
    const float* xpre = (dir == 0) ? &g_Xpre[0][t][0][0]
                                   : &g_Xpre[1][TT - 1 - t][0][0];

    __shared__ uint32_t sA[64][36];
    __shared__ uint32_t sB[64][36];

    const int tid  = threadIdx.x;
    const int warp = tid >> 5;
    const int lane = tid & 31;

    float acc[8][4];
#pragma unroll
    for (int i = 0; i < 8; i++)
#pragma unroll
        for (int e = 0; e < 4; e++) acc[i][e] = 0.0f;

    for (int k0 = 0; k0 < HID; k0 += 32) {
        // A: rows = batch b, hin[b*HID + k]
        for (int i = tid; i < 512; i += 128) {
            int r = i >> 3, c = (i & 7) * 4;
            float4 v = *(const float4*)&hin[(size_t)r * HID + k0 + c];
            sA[r][c + 0] = f2tf32(v.x);
            sA[r][c + 1] = f2tf32(v.y);
            sA[r][c + 2] = f2tf32(v.z);
            sA[r][c + 3] = f2tf32(v.w);
        }
        // B: row r -> W_hh row (gate*1024 + j0 + (r&15)), gate = r>>4
        for (int i = tid; i < 512; i += 128) {
            int r = i >> 3, c = (i & 7) * 4;
            int gn = (r >> 4) * HID + j0 + (r & 15);
            float4 v = *(const float4*)&Whh[(size_t)gn * HID + k0 + c];
            sB[r][c + 0] = f2tf32(v.x);
            sB[r][c + 1] = f2tf32(v.y);
            sB[r][c + 2] = f2tf32(v.z);
            sB[r][c + 3] = f2tf32(v.w);
        }
        __syncthreads();
#pragma unroll
        for (int kk = 0; kk < 32; kk += 8) {
            uint32_t a0 = sA[warp * 16 + (lane >> 2)    ][kk + (lane & 3)];
            uint32_t a1 = sA[warp * 16 + (lane >> 2) + 8][kk + (lane & 3)];
            uint32_t a2 = sA[warp * 16 + (lane >> 2)    ][kk + (lane & 3) + 4];
            uint32_t a3 = sA[warp * 16 + (lane >> 2) + 8][kk + (lane & 3) + 4];
#pragma unroll
            for (int nf = 0; nf < 8; nf++) {
                uint32_t b0 = sB[nf * 8 + (lane >> 2)][kk + (lane & 3)];
                uint32_t b1 = sB[nf * 8 + (lane >> 2)][kk + (lane & 3) + 4];
                mma_tf32(acc[nf], a0, a1, a2, a3, b0, b1);
            }
        }
        __syncthreads();
    }

    // Fused epilogue: tile cols 0..15 = gate i, 16..31 = f, 32..47 = g, 48..63 = o.
    // Thread owning col c in frag nf also owns c+16 in frag nf+2, etc.
    const int r_lo = warp * 16 + (lane >> 2);
#pragma unroll
    for (int nf = 0; nf < 2; nf++) {
#pragma unroll
        for (int e = 0; e < 4; e++) {
            int b  = r_lo + ((e >> 1) << 3);
            int jj = nf * 8 + (lane & 3) * 2 + (e & 1);
            int j  = j0 + jj;
            float vi = acc[nf    ][e] + xpre[(size_t)b * G4 + j];
            float vf = acc[nf + 2][e] + xpre[(size_t)b * G4 + HID + j];
            float vg = acc[nf + 4][e] + xpre[(size_t)b * G4 + 2 * HID + j];
            float vo = acc[nf + 6][e] + xpre[(size_t)b * G4 + 3 * HID + j];
            float co = g_c[dir][b][j];
            float cn = sigf(vf) * co + sigf(vi) * tanhf(vg);
            float hn = sigf(vo) * tanhf(cn);
            g_c[dir][b][j] = cn;
            hout[(size_t)b * HID + j] = hn;
            // hidden_states (B, T, 2H): fwd slot t, bwd slot t (traversal order)
            out[((size_t)b * TT + t) * (2 * HID) + dir * HID + j] = hn;
        }
    }
}

// ---------------- final FCs: tanh(concat @ W^T + b) ----------------
// grid: (16 n-tiles, 2 which), block 256. which=0: hiddens (fh), which=1: cells (fc)
__global__ void __launch_bounds__(256) final_fc(
    const float* __restrict__ fhW, const float* __restrict__ fhb,
    const float* __restrict__ fcW, const float* __restrict__ fcb,
    float* __restrict__ out) {
    const int which = blockIdx.y;
    const int n0 = blockIdx.x * 64;
    const float* W  = which ? fcW : fhW;
    const float* bb = which ? fcb : fhb;

    __shared__ float sA[64][33];
    __shared__ float sB[64][33];

    const int tid = threadIdx.x;
    const int rb = (tid >> 4) * 4;
    const int cb = (tid & 15) * 4;
    float acc[4][4] = {};

    for (int k0 = 0; k0 < 2 * HID; k0 += 32) {
        int dir = k0 >> 10, kk0 = k0 & (HID - 1);
        const float* src = which ? &g_c[dir][0][0] : &g_h[0][dir][0][0];
        for (int i = tid; i < 512; i += 256) {
            int r = i >> 3, c = (i & 7) * 4;
            float4 v = *(const float4*)&src[(size_t)r * HID + kk0 + c];
            sA[r][c] = v.x; sA[r][c + 1] = v.y; sA[r][c + 2] = v.z; sA[r][c + 3] = v.w;
        }
        for (int i = tid; i < 512; i += 256) {
            int r = i >> 3, c = (i & 7) * 4;
            float4 v = *(const float4*)&W[(size_t)(n0 + r) * (2 * HID) + k0 + c];
            sB[r][c] = v.x; sB[r][c + 1] = v.y; sB[r][c + 2] = v.z; sB[r][c + 3] = v.w;
        }
        __syncthreads();
#pragma unroll
        for (int k = 0; k < 32; k++)
#pragma unroll
            for (int i = 0; i < 4; i++)
#pragma unroll
                for (int j = 0; j < 4; j++)
                    acc[i][j] += sA[rb + i][k] * sB[cb + j][k];
        __syncthreads();
    }

    size_t base = (size_t)BATCH * TT * 2 * HID + (size_t)which * BATCH * DDEC;
#pragma unroll
    for (int i = 0; i < 4; i++)
#pragma unroll
        for (int j = 0; j < 4; j++) {
            int n = n0 + cb + j;
            out[base + (size_t)(rb + i) * DDEC + n] = tanhf(acc[i][j] + bb[n]);
        }
}

// ---------------- entry ----------------
extern "C" void kernel_launch(void* const* d_in, const int* in_sizes, int n_in,
                              void* d_out, int out_size) {
    const float* X     = (const float*)d_in[0];
    const float* Wih_f = (const float*)d_in[1];
    const float* Whh_f = (const float*)d_in[2];
    const float* bih_f = (const float*)d_in[3];
    const float* bhh_f = (const float*)d_in[4];
    const float* Wih_b = (const float*)d_in[5];
    const float* Whh_b = (const float*)d_in[6];
    const float* bih_b = (const float*)d_in[7];
    const float* bhh_b = (const float*)d_in[8];
    const float* fc_W  = (const float*)d_in[9];
    const float* fc_b  = (const float*)d_in[10];
    const float* fh_W  = (const float*)d_in[11];
    const float* fh_b  = (const float*)d_in[12];
    float* out = (float*)d_out;

    init_states<<<512, 256>>>();
    gemm_xpre<<<dim3(64, 512, 2), 128>>>(X, Wih_f, Wih_b, bih_f, bhh_f, bih_b, bhh_b);
    for (int t = 0; t < TT; t++)
        lstm_step<<<dim3(64, 2), 128>>>(Whh_f, Whh_b, t, out);
    final_fc<<<dim3(16, 2), 256>>>(fh_W, fh_b, fc_W, fc_b, out);
}

// round 4
// speedup vs baseline: 2.9220x; 2.9220x over previous
#include <cuda_runtime.h>
#include <cstdint>
#include <cstdio>

#define BATCH 64
#define TT    512
#define DIN   512
#define HID   1024
#define G4    4096
#define DDEC  1024

// ---------------- device scratch (static, allocation-free) ----------------
__device__ float    g_Xpre[2][TT][BATCH][G4];        // 1 GiB
__device__ uint32_t g_htf[2][2][BATCH][HID];         // h as tf32 bits, ping-pong
__device__ float    g_c[2][BATCH][HID];              // cell state fp32
__device__ uint32_t g_Wtf[2][G4 * HID];              // W_hh pre-converted to tf32

// ---------------- helpers ----------------
__device__ __forceinline__ uint32_t f2tf32(float x) {
    uint32_t r;
    asm("cvt.rna.tf32.f32 %0, %1;" : "=r"(r) : "f"(x));
    return r;
}

__device__ __forceinline__ void mma_tf32(float* c,
                                         uint32_t a0, uint32_t a1, uint32_t a2, uint32_t a3,
                                         uint32_t b0, uint32_t b1) {
    asm volatile(
        "mma.sync.aligned.m16n8k8.row.col.f32.tf32.tf32.f32 "
        "{%0,%1,%2,%3}, {%4,%5,%6,%7}, {%8,%9}, {%0,%1,%2,%3};"
        : "+f"(c[0]), "+f"(c[1]), "+f"(c[2]), "+f"(c[3])
        : "r"(a0), "r"(a1), "r"(a2), "r"(a3), "r"(b0), "r"(b1));
}

__device__ __forceinline__ float sigf(float x) { return 1.0f / (1.0f + expf(-x)); }

#define CP_ASYNC16(sa, ga) asm volatile("cp.async.ca.shared.global [%0], [%1], 16;\n" :: "r"(sa), "l"(ga))
#define CP_COMMIT()        asm volatile("cp.async.commit_group;\n" ::)
#define CP_WAIT2()         asm volatile("cp.async.wait_group 2;\n" ::)

// ---------------- init: zero h (parity 0, tf32 bits) and c ----------------
__global__ void init_states() {
    int i = blockIdx.x * blockDim.x + threadIdx.x;   // 0 .. 131071
    ((uint32_t*)g_htf)[i] = 0u;                      // zeroes g_htf[0][*][*][*]
    ((float*)g_c)[i] = 0.0f;
}

// ---------------- one-time: W_hh -> tf32 bits ----------------
__global__ void __launch_bounds__(256) cvt_weights(
    const float* __restrict__ Wf, const float* __restrict__ Wb) {
    const int dir = blockIdx.y;
    const float* src = dir ? Wb : Wf;
    size_t i = ((size_t)blockIdx.x * 256 + threadIdx.x) * 4;
    float4 v = *(const float4*)(src + i);
    uint32_t* d = &g_Wtf[dir][i];
    d[0] = f2tf32(v.x); d[1] = f2tf32(v.y);
    d[2] = f2tf32(v.z); d[3] = f2tf32(v.w);
}

// ---------------- big GEMM: Xpre = X @ W_ih^T + (b_ih + b_hh) ----------------
// (unchanged from passing R3 kernel)
__global__ void __launch_bounds__(128) gemm_xpre(
    const float* __restrict__ X,
    const float* __restrict__ Wih_f, const float* __restrict__ Wih_b,
    const float* __restrict__ bih_f, const float* __restrict__ bhh_f,
    const float* __restrict__ bih_b, const float* __restrict__ bhh_b) {
    const int nt  = blockIdx.x;
    const int t   = blockIdx.y;
    const int dir = blockIdx.z;
    const float* W  = dir ? Wih_b : Wih_f;
    const float* bi = dir ? bih_b : bih_f;
    const float* bh = dir ? bhh_b : bhh_f;
    const int n0 = nt * 64;

    __shared__ uint32_t sA[64][36];
    __shared__ uint32_t sB[64][36];

    const int tid  = threadIdx.x;
    const int warp = tid >> 5;
    const int lane = tid & 31;

    float acc[8][4];
#pragma unroll
    for (int i = 0; i < 8; i++)
#pragma unroll
        for (int e = 0; e < 4; e++) acc[i][e] = 0.0f;

    for (int k0 = 0; k0 < DIN; k0 += 32) {
        for (int i = tid; i < 512; i += 128) {
            int r = i >> 3, c = (i & 7) * 4;
            float4 v = *(const float4*)&X[((size_t)r * TT + t) * DIN + k0 + c];
            sA[r][c + 0] = f2tf32(v.x);
            sA[r][c + 1] = f2tf32(v.y);
            sA[r][c + 2] = f2tf32(v.z);
            sA[r][c + 3] = f2tf32(v.w);
        }
        for (int i = tid; i < 512; i += 128) {
            int r = i >> 3, c = (i & 7) * 4;
            float4 v = *(const float4*)&W[(size_t)(n0 + r) * DIN + k0 + c];
            sB[r][c + 0] = f2tf32(v.x);
            sB[r][c + 1] = f2tf32(v.y);
            sB[r][c + 2] = f2tf32(v.z);
            sB[r][c + 3] = f2tf32(v.w);
        }
        __syncthreads();
#pragma unroll
        for (int kk = 0; kk < 32; kk += 8) {
            uint32_t a0 = sA[warp * 16 + (lane >> 2)    ][kk + (lane & 3)];
            uint32_t a1 = sA[warp * 16 + (lane >> 2) + 8][kk + (lane & 3)];
            uint32_t a2 = sA[warp * 16 + (lane >> 2)    ][kk + (lane & 3) + 4];
            uint32_t a3 = sA[warp * 16 + (lane >> 2) + 8][kk + (lane & 3) + 4];
#pragma unroll
            for (int nf = 0; nf < 8; nf++) {
                uint32_t b0 = sB[nf * 8 + (lane >> 2)][kk + (lane & 3)];
                uint32_t b1 = sB[nf * 8 + (lane >> 2)][kk + (lane & 3) + 4];
                mma_tf32(acc[nf], a0, a1, a2, a3, b0, b1);
            }
        }
        __syncthreads();
    }

    float* dst = &g_Xpre[dir][t][0][0];
    const int r_lo = warp * 16 + (lane >> 2);
#pragma unroll
    for (int nf = 0; nf < 8; nf++) {
        int c0 = n0 + nf * 8 + (lane & 3) * 2;
        float bias0 = bi[c0] + bh[c0];
        float bias1 = bi[c0 + 1] + bh[c0 + 1];
        dst[(size_t)r_lo * G4 + c0]           = acc[nf][0] + bias0;
        dst[(size_t)r_lo * G4 + c0 + 1]       = acc[nf][1] + bias1;
        dst[(size_t)(r_lo + 8) * G4 + c0]     = acc[nf][2] + bias0;
        dst[(size_t)(r_lo + 8) * G4 + c0 + 1] = acc[nf][3] + bias1;
    }
}

// ---------------- per-timestep fused kernel, v2 (pipelined) ----------------
// grid (32 j-tiles of 32 hidden units, 2 dirs) = 64 blocks, 256 threads (8 warps).
// Block tile: M=64 (batch) x N=128 gate cols. Warp: warpM = warp&3 (16 rows),
// warpN = warp>>2 (one 16-j group, 64 gate cols) -> gate fusion preserved.
// K=1024 streamed in 32 chunks of 32 via 4-stage cp.async pipeline.
// SMEM per stage: A[64][36] + B[128][36] u32 (stride 36 => conflict-free frags).
#define STG_U32   6912          // (64+128)*36
#define STG_BYTES 27648
#define B_OFF_U32 2304          // 64*36

__global__ void __launch_bounds__(256, 1) lstm_step(int t, float* __restrict__ out) {
    const int dir = blockIdx.y;
    const int j0  = blockIdx.x * 32;
    const int par = t & 1;
    const uint32_t* hin  = &g_htf[par][dir][0][0];
    uint32_t*       houtf = &g_htf[par ^ 1][dir][0][0];
    const uint32_t* Wtf  = &g_Wtf[dir][0];
    const float* xpre = (dir == 0) ? &g_Xpre[0][t][0][0]
                                   : &g_Xpre[1][TT - 1 - t][0][0];

    extern __shared__ uint32_t smem[];
    const uint32_t sbase = (uint32_t)__cvta_generic_to_shared(smem);

    const int tid   = threadIdx.x;
    const int warp  = tid >> 5;
    const int lane  = tid & 31;
    const int warpM = warp & 3;
    const int warpN = warp >> 2;
    const int m0    = warpM * 16;
    const int nbase = warpN * 64;

    // --- producer setup: 6 cp.async (16B) per thread per stage ---
    uint32_t soff[6];
    const uint32_t* gb[6];
#pragma unroll
    for (int q = 0; q < 6; q++) {
        int i = tid + q * 256;
        if (i < 512) {                       // A tile: 64 rows x 32 k
            int r = i >> 3, sg = i & 7;
            soff[q] = (uint32_t)(r * 36 + sg * 4) * 4u;
            gb[q]   = hin + (size_t)r * HID + sg * 4;
        } else {                             // B tile: 128 gate-col rows x 32 k
            int j  = i - 512;
            int c  = j >> 3, sg = j & 7;
            int wg = c >> 6, rem = c & 63;
            int gate = rem >> 4, jl = rem & 15;
            int gn = gate * HID + j0 + wg * 16 + jl;
            soff[q] = (uint32_t)(B_OFF_U32 + c * 36 + sg * 4) * 4u;
            gb[q]   = Wtf + (size_t)gn * HID + sg * 4;
        }
    }

    float acc[8][4];
#pragma unroll
    for (int i = 0; i < 8; i++)
#pragma unroll
        for (int e = 0; e < 4; e++) acc[i][e] = 0.0f;

    // --- prologue: fill 3 stages ---
#pragma unroll
    for (int s = 0; s < 3; s++) {
        uint32_t sb = sbase + s * STG_BYTES;
        int k0 = s * 32;
#pragma unroll
        for (int q = 0; q < 6; q++) CP_ASYNC16(sb + soff[q], gb[q] + k0);
        CP_COMMIT();
    }

    // --- main loop: 32 K-chunks ---
    for (int it = 0; it < 32; it++) {
        CP_WAIT2();
        __syncthreads();

        const uint32_t* A = smem + (it & 3) * STG_U32;
        const uint32_t* B = A + B_OFF_U32;
#pragma unroll
        for (int kk = 0; kk < 32; kk += 8) {
            const uint32_t* ar = A + (m0 + (lane >> 2)) * 36 + kk + (lane & 3);
            uint32_t a0 = ar[0];
            uint32_t a1 = ar[8 * 36];
            uint32_t a2 = ar[4];
            uint32_t a3 = ar[8 * 36 + 4];
#pragma unroll
            for (int nf = 0; nf < 8; nf++) {
                const uint32_t* br = B + (nbase + nf * 8 + (lane >> 2)) * 36 + kk + (lane & 3);
                mma_tf32(acc[nf], a0, a1, a2, a3, br[0], br[4]);
            }
        }

        if (it + 3 < 32) {
            uint32_t sb = sbase + ((it + 3) & 3) * STG_BYTES;
            int k0 = (it + 3) * 32;
#pragma unroll
            for (int q = 0; q < 6; q++) CP_ASYNC16(sb + soff[q], gb[q] + k0);
        }
        CP_COMMIT();
    }

    // --- fused LSTM epilogue ---
#pragma unroll
    for (int nf = 0; nf < 2; nf++) {
#pragma unroll
        for (int e = 0; e < 4; e++) {
            int b  = m0 + (lane >> 2) + ((e >> 1) << 3);
            int jl = nf * 8 + (lane & 3) * 2 + (e & 1);
            int j  = j0 + warpN * 16 + jl;
            float vi = acc[nf    ][e] + xpre[(size_t)b * G4 + j];
            float vf = acc[nf + 2][e] + xpre[(size_t)b * G4 + HID + j];
            float vg = acc[nf + 4][e] + xpre[(size_t)b * G4 + 2 * HID + j];
            float vo = acc[nf + 6][e] + xpre[(size_t)b * G4 + 3 * HID + j];
            float co = g_c[dir][b][j];
            float cn = sigf(vf) * co + sigf(vi) * tanhf(vg);
            float hn = sigf(vo) * tanhf(cn);
            g_c[dir][b][j] = cn;
            houtf[(size_t)b * HID + j] = f2tf32(hn);
            out[((size_t)b * TT + t) * (2 * HID) + dir * HID + j] = hn;
        }
    }
}

// ---------------- final FCs: tanh(concat @ W^T + b) ----------------
// which=0: hiddens (fh) -- h_T read from out[t = T-1]; which=1: cells (fc) from g_c.
__global__ void __launch_bounds__(256) final_fc(
    const float* __restrict__ fhW, const float* __restrict__ fhb,
    const float* __restrict__ fcW, const float* __restrict__ fcb,
    float* __restrict__ out) {
    const int which = blockIdx.y;
    const int n0 = blockIdx.x * 64;
    const float* W  = which ? fcW : fhW;
    const float* bb = which ? fcb : fhb;

    __shared__ float sA[64][33];
    __shared__ float sB[64][33];

    const int tid = threadIdx.x;
    const int rb = (tid >> 4) * 4;
    const int cb = (tid & 15) * 4;
    float acc[4][4] = {};

    for (int k0 = 0; k0 < 2 * HID; k0 += 32) {
        for (int i = tid; i < 512; i += 256) {
            int r = i >> 3, c = (i & 7) * 4;
            float4 v;
            if (which == 0) {
                v = *(const float4*)&out[((size_t)r * TT + (TT - 1)) * (2 * HID) + k0 + c];
            } else {
                int dir = k0 >> 10, kk0 = k0 & (HID - 1);
                v = *(const float4*)&g_c[dir][r][kk0 + c];
            }
            sA[r][c] = v.x; sA[r][c + 1] = v.y; sA[r][c + 2] = v.z; sA[r][c + 3] = v.w;
        }
        for (int i = tid; i < 512; i += 256) {
            int r = i >> 3, c = (i & 7) * 4;
            float4 v = *(const float4*)&W[(size_t)(n0 + r) * (2 * HID) + k0 + c];
            sB[r][c] = v.x; sB[r][c + 1] = v.y; sB[r][c + 2] = v.z; sB[r][c + 3] = v.w;
        }
        __syncthreads();
#pragma unroll
        for (int k = 0; k < 32; k++)
#pragma unroll
            for (int i = 0; i < 4; i++)
#pragma unroll
                for (int j = 0; j < 4; j++)
                    acc[i][j] += sA[rb + i][k] * sB[cb + j][k];
        __syncthreads();
    }

    size_t base = (size_t)BATCH * TT * 2 * HID + (size_t)which * BATCH * DDEC;
#pragma unroll
    for (int i = 0; i < 4; i++)
#pragma unroll
        for (int j = 0; j < 4; j++) {
            int n = n0 + cb + j;
            out[base + (size_t)(rb + i) * DDEC + n] = tanhf(acc[i][j] + bb[n]);
        }
}

// ---------------- entry ----------------
extern "C" void kernel_launch(void* const* d_in, const int* in_sizes, int n_in,
                              void* d_out, int out_size) {
    const float* X     = (const float*)d_in[0];
    const float* Wih_f = (const float*)d_in[1];
    const float* Whh_f = (const float*)d_in[2];
    const float* bih_f = (const float*)d_in[3];
    const float* bhh_f = (const float*)d_in[4];
    const float* Wih_b = (const float*)d_in[5];
    const float* Whh_b = (const float*)d_in[6];
    const float* bih_b = (const float*)d_in[7];
    const float* bhh_b = (const float*)d_in[8];
    const float* fc_W  = (const float*)d_in[9];
    const float* fc_b  = (const float*)d_in[10];
    const float* fh_W  = (const float*)d_in[11];
    const float* fh_b  = (const float*)d_in[12];
    float* out = (float*)d_out;

    static bool attr_set = false;
    if (!attr_set) {
        cudaFuncSetAttribute(lstm_step, cudaFuncAttributeMaxDynamicSharedMemorySize,
                             4 * STG_BYTES);
        attr_set = true;
    }

    init_states<<<512, 256>>>();
    cvt_weights<<<dim3(G4 * HID / 1024, 2), 256>>>(Whh_f, Whh_b);
    gemm_xpre<<<dim3(64, 512, 2), 128>>>(X, Wih_f, Wih_b, bih_f, bhh_f, bih_b, bhh_b);
    for (int t = 0; t < TT; t++)
        lstm_step<<<dim3(32, 2), 256, 4 * STG_BYTES>>>(t, out);
    final_fc<<<dim3(16, 2), 256>>>(fh_W, fh_b, fc_W, fc_b, out);
}

// round 5
// speedup vs baseline: 4.2271x; 1.4466x over previous
#include <cuda_runtime.h>
#include <cstdint>

#define BATCH 64
#define TT    512
#define DIN   512
#define HID   1024
#define G4    4096
#define DDEC  1024

// ---------------- device scratch (static, allocation-free) ----------------
__device__ float    g_Xpre[2][TT][BATCH][G4];        // 1 GiB
__device__ uint32_t g_htf[2][2][BATCH][HID];         // h as tf32 bits, ping-pong
__device__ float    g_c[2][BATCH][HID];              // final cell state (written once)
__device__ uint32_t g_Wtf[2][G4 * HID];              // W_hh pre-converted to tf32
__device__ unsigned g_bar[2];                        // per-direction step barrier

// ---------------- helpers ----------------
__device__ __forceinline__ uint32_t f2tf32(float x) {
    uint32_t r;
    asm("cvt.rna.tf32.f32 %0, %1;" : "=r"(r) : "f"(x));
    return r;
}

__device__ __forceinline__ void mma_tf32(float* c,
                                         uint32_t a0, uint32_t a1, uint32_t a2, uint32_t a3,
                                         uint32_t b0, uint32_t b1) {
    asm volatile(
        "mma.sync.aligned.m16n8k8.row.col.f32.tf32.tf32.f32 "
        "{%0,%1,%2,%3}, {%4,%5,%6,%7}, {%8,%9}, {%0,%1,%2,%3};"
        : "+f"(c[0]), "+f"(c[1]), "+f"(c[2]), "+f"(c[3])
        : "r"(a0), "r"(a1), "r"(a2), "r"(a3), "r"(b0), "r"(b1));
}

__device__ __forceinline__ float sigf(float x) { return 1.0f / (1.0f + expf(-x)); }

#define CP_CG(sa, ga)  asm volatile("cp.async.cg.shared.global [%0], [%1], 16;\n" :: "r"(sa), "l"(ga))
#define CP_CA(sa, ga)  asm volatile("cp.async.ca.shared.global [%0], [%1], 16;\n" :: "r"(sa), "l"(ga))
#define CP_COMMIT()    asm volatile("cp.async.commit_group;\n" ::)
#define CP_WAIT2()     asm volatile("cp.async.wait_group 2;\n" ::)

// ---------------- init: zero h parity-0 (tf32 bits) + barrier ----------------
__global__ void init_states() {
    int i = blockIdx.x * blockDim.x + threadIdx.x;   // 0 .. 131071
    ((uint32_t*)g_htf)[i] = 0u;                      // zeroes g_htf[0][*][*][*]
    if (i < 2) g_bar[i] = 0u;
}

// ---------------- one-time: W_hh -> tf32 bits ----------------
__global__ void __launch_bounds__(256) cvt_weights(
    const float* __restrict__ Wf, const float* __restrict__ Wb) {
    const int dir = blockIdx.y;
    const float* src = dir ? Wb : Wf;
    size_t i = ((size_t)blockIdx.x * 256 + threadIdx.x) * 4;
    float4 v = *(const float4*)(src + i);
    uint32_t* d = &g_Wtf[dir][i];
    d[0] = f2tf32(v.x); d[1] = f2tf32(v.y);
    d[2] = f2tf32(v.z); d[3] = f2tf32(v.w);
}

// ---------------- big GEMM: Xpre = X @ W_ih^T + (b_ih + b_hh) ----------------
__global__ void __launch_bounds__(128) gemm_xpre(
    const float* __restrict__ X,
    const float* __restrict__ Wih_f, const float* __restrict__ Wih_b,
    const float* __restrict__ bih_f, const float* __restrict__ bhh_f,
    const float* __restrict__ bih_b, const float* __restrict__ bhh_b) {
    const int nt  = blockIdx.x;
    const int t   = blockIdx.y;
    const int dir = blockIdx.z;
    const float* W  = dir ? Wih_b : Wih_f;
    const float* bi = dir ? bih_b : bih_f;
    const float* bh = dir ? bhh_b : bhh_f;
    const int n0 = nt * 64;

    __shared__ uint32_t sA[64][36];
    __shared__ uint32_t sB[64][36];

    const int tid  = threadIdx.x;
    const int warp = tid >> 5;
    const int lane = tid & 31;

    float acc[8][4];
#pragma unroll
    for (int i = 0; i < 8; i++)
#pragma unroll
        for (int e = 0; e < 4; e++) acc[i][e] = 0.0f;

    for (int k0 = 0; k0 < DIN; k0 += 32) {
        for (int i = tid; i < 512; i += 128) {
            int r = i >> 3, c = (i & 7) * 4;
            float4 v = *(const float4*)&X[((size_t)r * TT + t) * DIN + k0 + c];
            sA[r][c + 0] = f2tf32(v.x);
            sA[r][c + 1] = f2tf32(v.y);
            sA[r][c + 2] = f2tf32(v.z);
            sA[r][c + 3] = f2tf32(v.w);
        }
        for (int i = tid; i < 512; i += 128) {
            int r = i >> 3, c = (i & 7) * 4;
            float4 v = *(const float4*)&W[(size_t)(n0 + r) * DIN + k0 + c];
            sB[r][c + 0] = f2tf32(v.x);
            sB[r][c + 1] = f2tf32(v.y);
            sB[r][c + 2] = f2tf32(v.z);
            sB[r][c + 3] = f2tf32(v.w);
        }
        __syncthreads();
#pragma unroll
        for (int kk = 0; kk < 32; kk += 8) {
            uint32_t a0 = sA[warp * 16 + (lane >> 2)    ][kk + (lane & 3)];
            uint32_t a1 = sA[warp * 16 + (lane >> 2) + 8][kk + (lane & 3)];
            uint32_t a2 = sA[warp * 16 + (lane >> 2)    ][kk + (lane & 3) + 4];
            uint32_t a3 = sA[warp * 16 + (lane >> 2) + 8][kk + (lane & 3) + 4];
#pragma unroll
            for (int nf = 0; nf < 8; nf++) {
                uint32_t b0 = sB[nf * 8 + (lane >> 2)][kk + (lane & 3)];
                uint32_t b1 = sB[nf * 8 + (lane >> 2)][kk + (lane & 3) + 4];
                mma_tf32(acc[nf], a0, a1, a2, a3, b0, b1);
            }
        }
        __syncthreads();
    }

    float* dst = &g_Xpre[dir][t][0][0];
    const int r_lo = warp * 16 + (lane >> 2);
#pragma unroll
    for (int nf = 0; nf < 8; nf++) {
        int c0 = n0 + nf * 8 + (lane & 3) * 2;
        float bias0 = bi[c0] + bh[c0];
        float bias1 = bi[c0 + 1] + bh[c0 + 1];
        dst[(size_t)r_lo * G4 + c0]           = acc[nf][0] + bias0;
        dst[(size_t)r_lo * G4 + c0 + 1]       = acc[nf][1] + bias1;
        dst[(size_t)(r_lo + 8) * G4 + c0]     = acc[nf][2] + bias0;
        dst[(size_t)(r_lo + 8) * G4 + c0 + 1] = acc[nf][3] + bias1;
    }
}

// ---------------- persistent LSTM: all 512 steps in one kernel ----------------
// Grid 128 = (64 j-tiles of 16 hidden units) x (2 dirs). 256 threads = 8 warps:
// warpM = warp&3 (16 batch rows), warpN = warp>>2 (8 j's x 4 gates = 32 cols).
// B-tile row c (0..63): gate = (c>>3)&3, j = j0 + (c>>5)*8 + (c&7)  -> warpN's
// frags nf=0..3 are exactly gates i,f,g,o for its 8 j's (gate fusion in regs).
// W_hh slice: K 0..511 resident in SMEM (stride 516, conflict-free); K 512..1023
// streamed per step via cp.async ring. h streamed per step via cp.async.cg
// (L1 bypass -- L1 is NOT flushed between steps inside one launch).
#define WRES_U32  (64 * 516)                 // 33024 u32 = 132096 B
#define HSTG_U32  (64 * 36)                  // 2304 u32 = 9216 B per stage
#define H_OFF_U32 WRES_U32
#define W_OFF_U32 (H_OFF_U32 + 4 * HSTG_U32) // 42240
#define SMEM_U32  (W_OFF_U32 + 4 * HSTG_U32) // 51456
#define SMEM_LSTM (SMEM_U32 * 4)             // 205824 B

__global__ void __launch_bounds__(256, 1) lstm_persistent(float* __restrict__ out) {
    const int bid = blockIdx.x;
    const int dir = bid >> 6;
    const int j0  = (bid & 63) * 16;
    const uint32_t* Wtf = &g_Wtf[dir][0];

    extern __shared__ uint32_t smem[];
    const uint32_t sbase = (uint32_t)__cvta_generic_to_shared(smem);

    const int tid   = threadIdx.x;
    const int warp  = tid >> 5;
    const int lane  = tid & 31;
    const int warpM = warp & 3;
    const int warpN = warp >> 2;
    const int m0    = warpM * 16;
    const int nbase = warpN * 32;

    // ---- load resident W half (K 0..511) into SMEM, stride 516 ----
    for (int i = tid; i < 64 * 128; i += 256) {
        int c = i >> 7, kq = (i & 127) * 4;
        int gate = (c >> 3) & 3, j = j0 + ((c >> 5) << 3) + (c & 7);
        uint4 v = *(const uint4*)&Wtf[(size_t)(gate * HID + j) * HID + kq];
        uint32_t* d = smem + c * 516 + kq;
        d[0] = v.x; d[1] = v.y; d[2] = v.z; d[3] = v.w;
    }

    // ---- per-thread cp.async setup (2x 16B per tile per chunk) ----
    uint32_t soffH[2], soffW[2], ghoff[2];
    const uint32_t* gWp[2];
#pragma unroll
    for (int q = 0; q < 2; q++) {
        int i = tid + q * 256;          // 0..511
        int r = i >> 3, sg = i & 7;
        soffH[q] = (uint32_t)(H_OFF_U32 + r * 36 + sg * 4) * 4u;
        ghoff[q] = (uint32_t)(r * HID + sg * 4);
        int gate = (r >> 3) & 3, j = j0 + ((r >> 5) << 3) + (r & 7);
        soffW[q] = (uint32_t)(W_OFF_U32 + r * 36 + sg * 4) * 4u;
        gWp[q]   = Wtf + (size_t)(gate * HID + j) * HID + sg * 4;
    }

    float creg[4] = {0.f, 0.f, 0.f, 0.f};
    __syncthreads();   // resident W visible

    for (int t = 0; t < TT; t++) {
        const uint32_t* hin  = &g_htf[t & 1][dir][0][0];
        uint32_t*       hout = &g_htf[(t & 1) ^ 1][dir][0][0];
        const float*    xpre = &g_Xpre[dir][dir ? (TT - 1 - t) : t][0][0];

        float acc[4][4];
#pragma unroll
        for (int i = 0; i < 4; i++)
#pragma unroll
            for (int e = 0; e < 4; e++) acc[i][e] = 0.0f;

        // prologue: h chunks 0..2
#pragma unroll
        for (int s = 0; s < 3; s++) {
#pragma unroll
            for (int q = 0; q < 2; q++)
                CP_CG(sbase + soffH[q] + s * (HSTG_U32 * 4), hin + ghoff[q] + s * 32);
            CP_COMMIT();
        }

        // ---- chunks 0..15: B from resident SMEM ----
        for (int it = 0; it < 16; it++) {
            CP_WAIT2();
            __syncthreads();
            const uint32_t* A = smem + H_OFF_U32 + (it & 3) * HSTG_U32;
#pragma unroll
            for (int kk = 0; kk < 32; kk += 8) {
                const uint32_t* ar = A + (m0 + (lane >> 2)) * 36 + kk + (lane & 3);
                uint32_t a0 = ar[0], a1 = ar[8 * 36], a2 = ar[4], a3 = ar[8 * 36 + 4];
#pragma unroll
                for (int nf = 0; nf < 4; nf++) {
                    const uint32_t* br = smem + (nbase + nf * 8 + (lane >> 2)) * 516
                                              + it * 32 + kk + (lane & 3);
                    mma_tf32(acc[nf], a0, a1, a2, a3, br[0], br[4]);
                }
            }
            int ch = it + 3;
#pragma unroll
            for (int q = 0; q < 2; q++)
                CP_CG(sbase + soffH[q] + (ch & 3) * (HSTG_U32 * 4), hin + ghoff[q] + ch * 32);
            if (ch >= 16) {
#pragma unroll
                for (int q = 0; q < 2; q++)
                    CP_CA(sbase + soffW[q] + (ch & 3) * (HSTG_U32 * 4), gWp[q] + ch * 32);
            }
            CP_COMMIT();
        }

        // ---- chunks 16..31: B from streamed ring ----
        for (int it = 16; it < 32; it++) {
            CP_WAIT2();
            __syncthreads();
            const uint32_t* A = smem + H_OFF_U32 + (it & 3) * HSTG_U32;
            const uint32_t* B = smem + W_OFF_U32 + (it & 3) * HSTG_U32;
#pragma unroll
            for (int kk = 0; kk < 32; kk += 8) {
                const uint32_t* ar = A + (m0 + (lane >> 2)) * 36 + kk + (lane & 3);
                uint32_t a0 = ar[0], a1 = ar[8 * 36], a2 = ar[4], a3 = ar[8 * 36 + 4];
#pragma unroll
                for (int nf = 0; nf < 4; nf++) {
                    const uint32_t* br = B + (nbase + nf * 8 + (lane >> 2)) * 36 + kk + (lane & 3);
                    mma_tf32(acc[nf], a0, a1, a2, a3, br[0], br[4]);
                }
            }
            int ch = it + 3;
            if (ch < 32) {
#pragma unroll
                for (int q = 0; q < 2; q++) {
                    CP_CG(sbase + soffH[q] + (ch & 3) * (HSTG_U32 * 4), hin + ghoff[q] + ch * 32);
                    CP_CA(sbase + soffW[q] + (ch & 3) * (HSTG_U32 * 4), gWp[q] + ch * 32);
                }
            }
            CP_COMMIT();
        }

        // ---- fused LSTM epilogue (cell state stays in registers) ----
#pragma unroll
        for (int e = 0; e < 4; e++) {
            int b = m0 + (lane >> 2) + ((e >> 1) << 3);
            int j = j0 + warpN * 8 + (lane & 3) * 2 + (e & 1);
            float vi = acc[0][e] + xpre[(size_t)b * G4 + j];
            float vf = acc[1][e] + xpre[(size_t)b * G4 + HID + j];
            float vg = acc[2][e] + xpre[(size_t)b * G4 + 2 * HID + j];
            float vo = acc[3][e] + xpre[(size_t)b * G4 + 3 * HID + j];
            float cn = sigf(vf) * creg[e] + sigf(vi) * tanhf(vg);
            float hn = sigf(vo) * tanhf(cn);
            creg[e] = cn;
            hout[(size_t)b * HID + j] = f2tf32(hn);
            out[((size_t)b * TT + t) * (2 * HID) + dir * HID + j] = hn;
        }

        // ---- grid barrier within this direction (64 blocks) ----
        __syncthreads();
        if (tid == 0) {
            __threadfence();
            atomicAdd(&g_bar[dir], 1u);
            unsigned target = 64u * (unsigned)(t + 1);
            volatile unsigned* p = &g_bar[dir];
            while (*p < target) {}
            __threadfence();
        }
        __syncthreads();
    }

    // write final cell state for final_fc
#pragma unroll
    for (int e = 0; e < 4; e++) {
        int b = m0 + (lane >> 2) + ((e >> 1) << 3);
        int j = j0 + warpN * 8 + (lane & 3) * 2 + (e & 1);
        g_c[dir][b][j] = creg[e];
    }
}

// ---------------- final FCs: tanh(concat @ W^T + b) ----------------
__global__ void __launch_bounds__(256) final_fc(
    const float* __restrict__ fhW, const float* __restrict__ fhb,
    const float* __restrict__ fcW, const float* __restrict__ fcb,
    float* __restrict__ out) {
    const int which = blockIdx.y;
    const int n0 = blockIdx.x * 64;
    const float* W  = which ? fcW : fhW;
    const float* bb = which ? fcb : fhb;

    __shared__ float sA[64][33];
    __shared__ float sB[64][33];

    const int tid = threadIdx.x;
    const int rb = (tid >> 4) * 4;
    const int cb = (tid & 15) * 4;
    float acc[4][4] = {};

    for (int k0 = 0; k0 < 2 * HID; k0 += 32) {
        for (int i = tid; i < 512; i += 256) {
            int r = i >> 3, c = (i & 7) * 4;
            float4 v;
            if (which == 0) {
                v = *(const float4*)&out[((size_t)r * TT + (TT - 1)) * (2 * HID) + k0 + c];
            } else {
                int dir = k0 >> 10, kk0 = k0 & (HID - 1);
                v = *(const float4*)&g_c[dir][r][kk0 + c];
            }
            sA[r][c] = v.x; sA[r][c + 1] = v.y; sA[r][c + 2] = v.z; sA[r][c + 3] = v.w;
        }
        for (int i = tid; i < 512; i += 256) {
            int r = i >> 3, c = (i & 7) * 4;
            float4 v = *(const float4*)&W[(size_t)(n0 + r) * (2 * HID) + k0 + c];
            sB[r][c] = v.x; sB[r][c + 1] = v.y; sB[r][c + 2] = v.z; sB[r][c + 3] = v.w;
        }
        __syncthreads();
#pragma unroll
        for (int k = 0; k < 32; k++)
#pragma unroll
            for (int i = 0; i < 4; i++)
#pragma unroll
                for (int j = 0; j < 4; j++)
                    acc[i][j] += sA[rb + i][k] * sB[cb + j][k];
        __syncthreads();
    }

    size_t base = (size_t)BATCH * TT * 2 * HID + (size_t)which * BATCH * DDEC;
#pragma unroll
    for (int i = 0; i < 4; i++)
#pragma unroll
        for (int j = 0; j < 4; j++) {
            int n = n0 + cb + j;
            out[base + (size_t)(rb + i) * DDEC + n] = tanhf(acc[i][j] + bb[n]);
        }
}

// ---------------- entry ----------------
extern "C" void kernel_launch(void* const* d_in, const int* in_sizes, int n_in,
                              void* d_out, int out_size) {
    const float* X     = (const float*)d_in[0];
    const float* Wih_f = (const float*)d_in[1];
    const float* Whh_f = (const float*)d_in[2];
    const float* bih_f = (const float*)d_in[3];
    const float* bhh_f = (const float*)d_in[4];
    const float* Wih_b = (const float*)d_in[5];
    const float* Whh_b = (const float*)d_in[6];
    const float* bih_b = (const float*)d_in[7];
    const float* bhh_b = (const float*)d_in[8];
    const float* fc_W  = (const float*)d_in[9];
    const float* fc_b  = (const float*)d_in[10];
    const float* fh_W  = (const float*)d_in[11];
    const float* fh_b  = (const float*)d_in[12];
    float* out = (float*)d_out;

    static bool attr_set = false;
    if (!attr_set) {
        cudaFuncSetAttribute(lstm_persistent, cudaFuncAttributeMaxDynamicSharedMemorySize,
                             SMEM_LSTM);
        attr_set = true;
    }

    init_states<<<512, 256>>>();
    cvt_weights<<<dim3(G4 * HID / 1024, 2), 256>>>(Whh_f, Whh_b);
    gemm_xpre<<<dim3(64, 512, 2), 128>>>(X, Wih_f, Wih_b, bih_f, bhh_f, bih_b, bhh_b);
    lstm_persistent<<<128, 256, SMEM_LSTM>>>(out);
    final_fc<<<dim3(16, 2), 256>>>(fh_W, fh_b, fc_W, fc_b, out);
}

// round 7
// speedup vs baseline: 4.2525x; 1.0060x over previous
#include <cuda_runtime.h>
#include <cstdint>

#define BATCH 64
#define TT    512
#define DIN   512
#define HID   1024
#define G4    4096
#define DDEC  1024

// ---------------- device scratch (static, allocation-free) ----------------
__device__ float    g_Xpre[2][TT][BATCH][G4];        // 1 GiB
__device__ uint32_t g_htf[2][2][BATCH][HID];         // h as tf32 bits, ping-pong
__device__ float    g_c[2][BATCH][HID];              // final cell state (written once)
__device__ uint32_t g_Wtf[2][G4 * HID];              // W_hh pre-converted to tf32
__device__ unsigned g_bar[2];                        // per-direction step barrier

// ---------------- helpers ----------------
__device__ __forceinline__ uint32_t f2tf32(float x) {
    uint32_t r;
    asm("cvt.rna.tf32.f32 %0, %1;" : "=r"(r) : "f"(x));
    return r;
}

__device__ __forceinline__ void mma_tf32(float* c,
                                         uint32_t a0, uint32_t a1, uint32_t a2, uint32_t a3,
                                         uint32_t b0, uint32_t b1) {
    asm volatile(
        "mma.sync.aligned.m16n8k8.row.col.f32.tf32.tf32.f32 "
        "{%0,%1,%2,%3}, {%4,%5,%6,%7}, {%8,%9}, {%0,%1,%2,%3};"
        : "+f"(c[0]), "+f"(c[1]), "+f"(c[2]), "+f"(c[3])
        : "r"(a0), "r"(a1), "r"(a2), "r"(a3), "r"(b0), "r"(b1));
}

__device__ __forceinline__ float sigf(float x) { return 1.0f / (1.0f + expf(-x)); }

#define CP_CG(sa, ga)  asm volatile("cp.async.cg.shared.global [%0], [%1], 16;\n" :: "r"(sa), "l"(ga))
#define CP_CA(sa, ga)  asm volatile("cp.async.ca.shared.global [%0], [%1], 16;\n" :: "r"(sa), "l"(ga))
#define CP_COMMIT()    asm volatile("cp.async.commit_group;\n" ::)
#define CP_WAIT2()     asm volatile("cp.async.wait_group 2;\n" ::)

// ---------------- init: zero h parity-0 (tf32 bits) + barrier ----------------
__global__ void init_states() {
    int i = blockIdx.x * blockDim.x + threadIdx.x;   // 0 .. 131071
    ((uint32_t*)g_htf)[i] = 0u;                      // zeroes g_htf[0][*][*][*]
    if (i < 2) g_bar[i] = 0u;
}

// ---------------- one-time: W_hh -> tf32 bits ----------------
__global__ void __launch_bounds__(256) cvt_weights(
    const float* __restrict__ Wf, const float* __restrict__ Wb) {
    const int dir = blockIdx.y;
    const float* src = dir ? Wb : Wf;
    size_t i = ((size_t)blockIdx.x * 256 + threadIdx.x) * 4;
    float4 v = *(const float4*)(src + i);
    uint32_t* d = &g_Wtf[dir][i];
    d[0] = f2tf32(v.x); d[1] = f2tf32(v.y);
    d[2] = f2tf32(v.z); d[3] = f2tf32(v.w);
}

// ---------------- big GEMM: Xpre = X @ W_ih^T + (b_ih + b_hh) ----------------
__global__ void __launch_bounds__(128) gemm_xpre(
    const float* __restrict__ X,
    const float* __restrict__ Wih_f, const float* __restrict__ Wih_b,
    const float* __restrict__ bih_f, const float* __restrict__ bhh_f,
    const float* __restrict__ bih_b, const float* __restrict__ bhh_b) {
    const int nt  = blockIdx.x;
    const int t   = blockIdx.y;
    const int dir = blockIdx.z;
    const float* W  = dir ? Wih_b : Wih_f;
    const float* bi = dir ? bih_b : bih_f;
    const float* bh = dir ? bhh_b : bhh_f;
    const int n0 = nt * 64;

    __shared__ uint32_t sA[64][36];
    __shared__ uint32_t sB[64][36];

    const int tid  = threadIdx.x;
    const int warp = tid >> 5;
    const int lane = tid & 31;

    float acc[8][4];
#pragma unroll
    for (int i = 0; i < 8; i++)
#pragma unroll
        for (int e = 0; e < 4; e++) acc[i][e] = 0.0f;

    for (int k0 = 0; k0 < DIN; k0 += 32) {
        for (int i = tid; i < 512; i += 128) {
            int r = i >> 3, c = (i & 7) * 4;
            float4 v = *(const float4*)&X[((size_t)r * TT + t) * DIN + k0 + c];
            sA[r][c + 0] = f2tf32(v.x);
            sA[r][c + 1] = f2tf32(v.y);
            sA[r][c + 2] = f2tf32(v.z);
            sA[r][c + 3] = f2tf32(v.w);
        }
        for (int i = tid; i < 512; i += 128) {
            int r = i >> 3, c = (i & 7) * 4;
            float4 v = *(const float4*)&W[(size_t)(n0 + r) * DIN + k0 + c];
            sB[r][c + 0] = f2tf32(v.x);
            sB[r][c + 1] = f2tf32(v.y);
            sB[r][c + 2] = f2tf32(v.z);
            sB[r][c + 3] = f2tf32(v.w);
        }
        __syncthreads();
#pragma unroll
        for (int kk = 0; kk < 32; kk += 8) {
            uint32_t a0 = sA[warp * 16 + (lane >> 2)    ][kk + (lane & 3)];
            uint32_t a1 = sA[warp * 16 + (lane >> 2) + 8][kk + (lane & 3)];
            uint32_t a2 = sA[warp * 16 + (lane >> 2)    ][kk + (lane & 3) + 4];
            uint32_t a3 = sA[warp * 16 + (lane >> 2) + 8][kk + (lane & 3) + 4];
#pragma unroll
            for (int nf = 0; nf < 8; nf++) {
                uint32_t b0 = sB[nf * 8 + (lane >> 2)][kk + (lane & 3)];
                uint32_t b1 = sB[nf * 8 + (lane >> 2)][kk + (lane & 3) + 4];
                mma_tf32(acc[nf], a0, a1, a2, a3, b0, b1);
            }
        }
        __syncthreads();
    }

    float* dst = &g_Xpre[dir][t][0][0];
    const int r_lo = warp * 16 + (lane >> 2);
#pragma unroll
    for (int nf = 0; nf < 8; nf++) {
        int c0 = n0 + nf * 8 + (lane & 3) * 2;
        float bias0 = bi[c0] + bh[c0];
        float bias1 = bi[c0 + 1] + bh[c0 + 1];
        dst[(size_t)r_lo * G4 + c0]           = acc[nf][0] + bias0;
        dst[(size_t)r_lo * G4 + c0 + 1]       = acc[nf][1] + bias1;
        dst[(size_t)(r_lo + 8) * G4 + c0]     = acc[nf][2] + bias0;
        dst[(size_t)(r_lo + 8) * G4 + c0 + 1] = acc[nf][3] + bias1;
    }
}

// ---------------- persistent LSTM: all 512 steps in one kernel ----------------
// Grid 128 = (64 j-tiles of 16 hidden units) x (2 dirs). 256 threads = 8 warps:
// warpM = warp&3 (16 batch rows), warpN = warp>>2 (8 j's x 4 gates = 32 cols).
// B-tile row c (0..63): gate = (c>>3)&3, j = j0 + (c>>5)*8 + (c&7)  -> warpN's
// frags nf=0..3 are exactly gates i,f,g,o for its 8 j's (gate fusion in regs).
// W_hh slice: K 0..511 resident in SMEM (stride 516, conflict-free); K 512..1023
// streamed per step via cp.async ring. h streamed per step via cp.async.cg
// (L1 bypass -- L1 is NOT flushed between steps inside one launch).
#define WRES_U32  (64 * 516)                 // 33024 u32 = 132096 B
#define HSTG_U32  (64 * 36)                  // 2304 u32 = 9216 B per stage
#define H_OFF_U32 WRES_U32
#define W_OFF_U32 (H_OFF_U32 + 4 * HSTG_U32) // 42240
#define SMEM_U32  (W_OFF_U32 + 4 * HSTG_U32) // 51456
#define SMEM_LSTM (SMEM_U32 * 4)             // 205824 B

__global__ void __launch_bounds__(256, 1) lstm_persistent(float* __restrict__ out) {
    const int bid = blockIdx.x;
    const int dir = bid >> 6;
    const int j0  = (bid & 63) * 16;
    const uint32_t* Wtf = &g_Wtf[dir][0];

    extern __shared__ uint32_t smem[];
    const uint32_t sbase = (uint32_t)__cvta_generic_to_shared(smem);

    const int tid   = threadIdx.x;
    const int warp  = tid >> 5;
    const int lane  = tid & 31;
    const int warpM = warp & 3;
    const int warpN = warp >> 2;
    const int m0    = warpM * 16;
    const int nbase = warpN * 32;

    // ---- load resident W half (K 0..511) into SMEM, stride 516 ----
    for (int i = tid; i < 64 * 128; i += 256) {
        int c = i >> 7, kq = (i & 127) * 4;
        int gate = (c >> 3) & 3, j = j0 + ((c >> 5) << 3) + (c & 7);
        uint4 v = *(const uint4*)&Wtf[(size_t)(gate * HID + j) * HID + kq];
        uint32_t* d = smem + c * 516 + kq;
        d[0] = v.x; d[1] = v.y; d[2] = v.z; d[3] = v.w;
    }

    // ---- per-thread cp.async setup (2x 16B per tile per chunk) ----
    uint32_t soffH[2], soffW[2], ghoff[2];
    const uint32_t* gWp[2];
#pragma unroll
    for (int q = 0; q < 2; q++) {
        int i = tid + q * 256;          // 0..511
        int r = i >> 3, sg = i & 7;
        soffH[q] = (uint32_t)(H_OFF_U32 + r * 36 + sg * 4) * 4u;
        ghoff[q] = (uint32_t)(r * HID + sg * 4);
        int gate = (r >> 3) & 3, j = j0 + ((r >> 5) << 3) + (r & 7);
        soffW[q] = (uint32_t)(W_OFF_U32 + r * 36 + sg * 4) * 4u;
        gWp[q]   = Wtf + (size_t)(gate * HID + j) * HID + sg * 4;
    }

    float creg[4] = {0.f, 0.f, 0.f, 0.f};
    __syncthreads();   // resident W visible

    for (int t = 0; t < TT; t++) {
        const uint32_t* hin  = &g_htf[t & 1][dir][0][0];
        uint32_t*       hout = &g_htf[(t & 1) ^ 1][dir][0][0];
        const float*    xpre = &g_Xpre[dir][dir ? (TT - 1 - t) : t][0][0];

        float acc[4][4];
#pragma unroll
        for (int i = 0; i < 4; i++)
#pragma unroll
            for (int e = 0; e < 4; e++) acc[i][e] = 0.0f;

        // prologue: h chunks 0..2
#pragma unroll
        for (int s = 0; s < 3; s++) {
#pragma unroll
            for (int q = 0; q < 2; q++)
                CP_CG(sbase + soffH[q] + s * (HSTG_U32 * 4), hin + ghoff[q] + s * 32);
            CP_COMMIT();
        }

        // ---- chunks 0..15: B from resident SMEM ----
        for (int it = 0; it < 16; it++) {
            CP_WAIT2();
            __syncthreads();
            const uint32_t* A = smem + H_OFF_U32 + (it & 3) * HSTG_U32;
#pragma unroll
            for (int kk = 0; kk < 32; kk += 8) {
                const uint32_t* ar = A + (m0 + (lane >> 2)) * 36 + kk + (lane & 3);
                uint32_t a0 = ar[0], a1 = ar[8 * 36], a2 = ar[4], a3 = ar[8 * 36 + 4];
#pragma unroll
                for (int nf = 0; nf < 4; nf++) {
                    const uint32_t* br = smem + (nbase + nf * 8 + (lane >> 2)) * 516
                                              + it * 32 + kk + (lane & 3);
                    mma_tf32(acc[nf], a0, a1, a2, a3, br[0], br[4]);
                }
            }
            int ch = it + 3;
#pragma unroll
            for (int q = 0; q < 2; q++)
                CP_CG(sbase + soffH[q] + (ch & 3) * (HSTG_U32 * 4), hin + ghoff[q] + ch * 32);
            if (ch >= 16) {
#pragma unroll
                for (int q = 0; q < 2; q++)
                    CP_CA(sbase + soffW[q] + (ch & 3) * (HSTG_U32 * 4), gWp[q] + ch * 32);
            }
            CP_COMMIT();
        }

        // ---- chunks 16..31: B from streamed ring ----
        for (int it = 16; it < 32; it++) {
            CP_WAIT2();
            __syncthreads();
            const uint32_t* A = smem + H_OFF_U32 + (it & 3) * HSTG_U32;
            const uint32_t* B = smem + W_OFF_U32 + (it & 3) * HSTG_U32;
#pragma unroll
            for (int kk = 0; kk < 32; kk += 8) {
                const uint32_t* ar = A + (m0 + (lane >> 2)) * 36 + kk + (lane & 3);
                uint32_t a0 = ar[0], a1 = ar[8 * 36], a2 = ar[4], a3 = ar[8 * 36 + 4];
#pragma unroll
                for (int nf = 0; nf < 4; nf++) {
                    const uint32_t* br = B + (nbase + nf * 8 + (lane >> 2)) * 36 + kk + (lane & 3);
                    mma_tf32(acc[nf], a0, a1, a2, a3, br[0], br[4]);
                }
            }
            int ch = it + 3;
            if (ch < 32) {
#pragma unroll
                for (int q = 0; q < 2; q++) {
                    CP_CG(sbase + soffH[q] + (ch & 3) * (HSTG_U32 * 4), hin + ghoff[q] + ch * 32);
                    CP_CA(sbase + soffW[q] + (ch & 3) * (HSTG_U32 * 4), gWp[q] + ch * 32);
                }
            }
            CP_COMMIT();
        }

        // ---- fused LSTM epilogue (cell state stays in registers) ----
#pragma unroll
        for (int e = 0; e < 4; e++) {
            int b = m0 + (lane >> 2) + ((e >> 1) << 3);
            int j = j0 + warpN * 8 + (lane & 3) * 2 + (e & 1);
            float vi = acc[0][e] + xpre[(size_t)b * G4 + j];
            float vf = acc[1][e] + xpre[(size_t)b * G4 + HID + j];
            float vg = acc[2][e] + xpre[(size_t)b * G4 + 2 * HID + j];
            float vo = acc[3][e] + xpre[(size_t)b * G4 + 3 * HID + j];
            float cn = sigf(vf) * creg[e] + sigf(vi) * tanhf(vg);
            float hn = sigf(vo) * tanhf(cn);
            creg[e] = cn;
            hout[(size_t)b * HID + j] = f2tf32(hn);
            out[((size_t)b * TT + t) * (2 * HID) + dir * HID + j] = hn;
        }

        // ---- grid barrier within this direction (64 blocks) ----
        __syncthreads();
        if (tid == 0) {
            __threadfence();
            atomicAdd(&g_bar[dir], 1u);
            unsigned target = 64u * (unsigned)(t + 1);
            volatile unsigned* p = &g_bar[dir];
            while (*p < target) {}
            __threadfence();
        }
        __syncthreads();
    }

    // write final cell state for final_fc
#pragma unroll
    for (int e = 0; e < 4; e++) {
        int b = m0 + (lane >> 2) + ((e >> 1) << 3);
        int j = j0 + warpN * 8 + (lane & 3) * 2 + (e & 1);
        g_c[dir][b][j] = creg[e];
    }
}

// ---------------- final FCs: tanh(concat @ W^T + b) ----------------
__global__ void __launch_bounds__(256) final_fc(
    const float* __restrict__ fhW, const float* __restrict__ fhb,
    const float* __restrict__ fcW, const float* __restrict__ fcb,
    float* __restrict__ out) {
    const int which = blockIdx.y;
    const int n0 = blockIdx.x * 64;
    const float* W  = which ? fcW : fhW;
    const float* bb = which ? fcb : fhb;

    __shared__ float sA[64][33];
    __shared__ float sB[64][33];

    const int tid = threadIdx.x;
    const int rb = (tid >> 4) * 4;
    const int cb = (tid & 15) * 4;
    float acc[4][4] = {};

    for (int k0 = 0; k0 < 2 * HID; k0 += 32) {
        for (int i = tid; i < 512; i += 256) {
            int r = i >> 3, c = (i & 7) * 4;
            float4 v;
            if (which == 0) {
                v = *(const float4*)&out[((size_t)r * TT + (TT - 1)) * (2 * HID) + k0 + c];
            } else {
                int dir = k0 >> 10, kk0 = k0 & (HID - 1);
                v = *(const float4*)&g_c[dir][r][kk0 + c];
            }
            sA[r][c] = v.x; sA[r][c + 1] = v.y; sA[r][c + 2] = v.z; sA[r][c + 3] = v.w;
        }
        for (int i = tid; i < 512; i += 256) {
            int r = i >> 3, c = (i & 7) * 4;
            float4 v = *(const float4*)&W[(size_t)(n0 + r) * (2 * HID) + k0 + c];
            sB[r][c] = v.x; sB[r][c + 1] = v.y; sB[r][c + 2] = v.z; sB[r][c + 3] = v.w;
        }
        __syncthreads();
#pragma unroll
        for (int k = 0; k < 32; k++)
#pragma unroll
            for (int i = 0; i < 4; i++)
#pragma unroll
                for (int j = 0; j < 4; j++)
                    acc[i][j] += sA[rb + i][k] * sB[cb + j][k];
        __syncthreads();
    }

    size_t base = (size_t)BATCH * TT * 2 * HID + (size_t)which * BATCH * DDEC;
#pragma unroll
    for (int i = 0; i < 4; i++)
#pragma unroll
        for (int j = 0; j < 4; j++) {
            int n = n0 + cb + j;
            out[base + (size_t)(rb + i) * DDEC + n] = tanhf(acc[i][j] + bb[n]);
        }
}

// ---------------- entry ----------------
extern "C" void kernel_launch(void* const* d_in, const int* in_sizes, int n_in,
                              void* d_out, int out_size) {
    const float* X     = (const float*)d_in[0];
    const float* Wih_f = (const float*)d_in[1];
    const float* Whh_f = (const float*)d_in[2];
    const float* bih_f = (const float*)d_in[3];
    const float* bhh_f = (const float*)d_in[4];
    const float* Wih_b = (const float*)d_in[5];
    const float* Whh_b = (const float*)d_in[6];
    const float* bih_b = (const float*)d_in[7];
    const float* bhh_b = (const float*)d_in[8];
    const float* fc_W  = (const float*)d_in[9];
    const float* fc_b  = (const float*)d_in[10];
    const float* fh_W  = (const float*)d_in[11];
    const float* fh_b  = (const float*)d_in[12];
    float* out = (float*)d_out;

    static bool attr_set = false;
    if (!attr_set) {
        cudaFuncSetAttribute(lstm_persistent, cudaFuncAttributeMaxDynamicSharedMemorySize,
                             SMEM_LSTM);
        attr_set = true;
    }

    init_states<<<512, 256>>>();
    cvt_weights<<<dim3(G4 * HID / 1024, 2), 256>>>(Whh_f, Whh_b);
    gemm_xpre<<<dim3(64, 512, 2), 128>>>(X, Wih_f, Wih_b, bih_f, bhh_f, bih_b, bhh_b);
    lstm_persistent<<<128, 256, SMEM_LSTM>>>(out);
    final_fc<<<dim3(16, 2), 256>>>(fh_W, fh_b, fc_W, fc_b, out);
}

// round 9
// speedup vs baseline: 4.3183x; 1.0155x over previous
#include <cuda_runtime.h>
#include <cstdint>

#define BATCH 64
#define TT    512
#define DIN   512
#define HID   1024
#define G4    4096
#define DDEC  1024

// ---------------- device scratch (static, allocation-free) ----------------
__device__ float    g_Xpre[2][TT][BATCH][G4];        // 1 GiB
__device__ uint32_t g_htf[2][2][BATCH][HID];         // h as tf32 bits, ping-pong
__device__ float    g_c[2][BATCH][HID];              // final cell state
__device__ uint32_t g_Wtf[2][G4 * HID];              // W_hh as tf32 bits
__device__ unsigned g_bar[2];                        // per-direction step barrier

// ---------------- helpers ----------------
__device__ __forceinline__ uint32_t f2tf32(float x) {
    uint32_t r;
    asm("cvt.rna.tf32.f32 %0, %1;" : "=r"(r) : "f"(x));
    return r;
}

__device__ __forceinline__ void mma_tf32(float* c,
                                         uint32_t a0, uint32_t a1, uint32_t a2, uint32_t a3,
                                         uint32_t b0, uint32_t b1) {
    asm volatile(
        "mma.sync.aligned.m16n8k8.row.col.f32.tf32.tf32.f32 "
        "{%0,%1,%2,%3}, {%4,%5,%6,%7}, {%8,%9}, {%0,%1,%2,%3};"
        : "+f"(c[0]), "+f"(c[1]), "+f"(c[2]), "+f"(c[3])
        : "r"(a0), "r"(a1), "r"(a2), "r"(a3), "r"(b0), "r"(b1));
}

__device__ __forceinline__ uint4 ldsm4(uint32_t a) {
    uint4 r;
    asm volatile("ldmatrix.sync.aligned.m8n8.x4.shared.b16 {%0,%1,%2,%3}, [%4];"
                 : "=r"(r.x), "=r"(r.y), "=r"(r.z), "=r"(r.w) : "r"(a));
    return r;
}

__device__ __forceinline__ float sigf(float x) { return 1.0f / (1.0f + expf(-x)); }

#define CP_CG(sa, ga)  asm volatile("cp.async.cg.shared.global [%0], [%1], 16;\n" :: "r"(sa), "l"(ga))
#define CP_CA(sa, ga)  asm volatile("cp.async.ca.shared.global [%0], [%1], 16;\n" :: "r"(sa), "l"(ga))
#define CP_COMMIT()    asm volatile("cp.async.commit_group;\n" ::)
#define CP_WAIT2()     asm volatile("cp.async.wait_group 2;\n" ::)

// ---------------- init ----------------
__global__ void init_states() {
    int i = blockIdx.x * blockDim.x + threadIdx.x;   // 0 .. 131071
    ((uint32_t*)g_htf)[i] = 0u;                      // zeroes g_htf[0][*][*][*]
    if (i < 2) g_bar[i] = 0u;
}

// ---------------- one-time: W_hh -> tf32 bits ----------------
__global__ void __launch_bounds__(256) cvt_weights(
    const float* __restrict__ Wf, const float* __restrict__ Wb) {
    const int dir = blockIdx.y;
    const float* src = dir ? Wb : Wf;
    size_t i = ((size_t)blockIdx.x * 256 + threadIdx.x) * 4;
    float4 v = *(const float4*)(src + i);
    uint32_t* d = &g_Wtf[dir][i];
    d[0] = f2tf32(v.x); d[1] = f2tf32(v.y);
    d[2] = f2tf32(v.z); d[3] = f2tf32(v.w);
}

// ---------------- big GEMM: Xpre = X @ W_ih^T + (b_ih + b_hh) ----------------
__global__ void __launch_bounds__(128) gemm_xpre(
    const float* __restrict__ X,
    const float* __restrict__ Wih_f, const float* __restrict__ Wih_b,
    const float* __restrict__ bih_f, const float* __restrict__ bhh_f,
    const float* __restrict__ bih_b, const float* __restrict__ bhh_b) {
    const int nt  = blockIdx.x;
    const int t   = blockIdx.y;
    const int dir = blockIdx.z;
    const float* W  = dir ? Wih_b : Wih_f;
    const float* bi = dir ? bih_b : bih_f;
    const float* bh = dir ? bhh_b : bhh_f;
    const int n0 = nt * 64;

    __shared__ uint32_t sA[64][36];
    __shared__ uint32_t sB[64][36];

    const int tid  = threadIdx.x;
    const int warp = tid >> 5;
    const int lane = tid & 31;

    float acc[8][4];
#pragma unroll
    for (int i = 0; i < 8; i++)
#pragma unroll
        for (int e = 0; e < 4; e++) acc[i][e] = 0.0f;

    for (int k0 = 0; k0 < DIN; k0 += 32) {
        for (int i = tid; i < 512; i += 128) {
            int r = i >> 3, c = (i & 7) * 4;
            float4 v = *(const float4*)&X[((size_t)r * TT + t) * DIN + k0 + c];
            sA[r][c + 0] = f2tf32(v.x);
            sA[r][c + 1] = f2tf32(v.y);
            sA[r][c + 2] = f2tf32(v.z);
            sA[r][c + 3] = f2tf32(v.w);
        }
        for (int i = tid; i < 512; i += 128) {
            int r = i >> 3, c = (i & 7) * 4;
            float4 v = *(const float4*)&W[(size_t)(n0 + r) * DIN + k0 + c];
            sB[r][c + 0] = f2tf32(v.x);
            sB[r][c + 1] = f2tf32(v.y);
            sB[r][c + 2] = f2tf32(v.z);
            sB[r][c + 3] = f2tf32(v.w);
        }
        __syncthreads();
#pragma unroll
        for (int kk = 0; kk < 32; kk += 8) {
            uint32_t a0 = sA[warp * 16 + (lane >> 2)    ][kk + (lane & 3)];
            uint32_t a1 = sA[warp * 16 + (lane >> 2) + 8][kk + (lane & 3)];
            uint32_t a2 = sA[warp * 16 + (lane >> 2)    ][kk + (lane & 3) + 4];
            uint32_t a3 = sA[warp * 16 + (lane >> 2) + 8][kk + (lane & 3) + 4];
#pragma unroll
            for (int nf = 0; nf < 8; nf++) {
                uint32_t b0 = sB[nf * 8 + (lane >> 2)][kk + (lane & 3)];
                uint32_t b1 = sB[nf * 8 + (lane >> 2)][kk + (lane & 3) + 4];
                mma_tf32(acc[nf], a0, a1, a2, a3, b0, b1);
            }
        }
        __syncthreads();
    }

    float* dst = &g_Xpre[dir][t][0][0];
    const int r_lo = warp * 16 + (lane >> 2);
#pragma unroll
    for (int nf = 0; nf < 8; nf++) {
        int c0 = n0 + nf * 8 + (lane & 3) * 2;
        float bias0 = bi[c0] + bh[c0];
        float bias1 = bi[c0 + 1] + bh[c0 + 1];
        dst[(size_t)r_lo * G4 + c0]           = acc[nf][0] + bias0;
        dst[(size_t)r_lo * G4 + c0 + 1]       = acc[nf][1] + bias1;
        dst[(size_t)(r_lo + 8) * G4 + c0]     = acc[nf][2] + bias0;
        dst[(size_t)(r_lo + 8) * G4 + c0 + 1] = acc[nf][3] + bias1;
    }
}

// ---------------- persistent LSTM v2 ----------------
// 128 blocks = 64 j-tiles x 2 dirs, 256 threads = 8 warps:
//   warpM = warp&1 (32 batch rows), warpN = (warp>>1)&1 (8 j x 4 gates),
//   kgrp  = warp>>2 (0: K 0..511 resident SMEM W, 1: K 512..1023 streamed W).
// Warp tile 32x32, ldmatrix.x4 loads, K-split partials reduced via SMEM.
// Ring: 3 slots x (hL 2304 + hH 2304 + Wstream 2304) u32, 2 bars/iter.
// xpre tile prefetched to SMEM one step ahead (issued during barrier poll).
#define WRES_U32  (64 * 516)                 // 33024 u32
#define SLOT_U32  6912                        // hL + hH + W chunk
#define RING_OFF  WRES_U32                    // 33024
#define RED_OFF   RING_OFF                    // reduce overlays ring (after last iter)
#define XP_OFF    (RING_OFF + 3 * SLOT_U32)   // 53760
#define SMEM_TOT  (XP_OFF + 64 * 68)          // 58112 u32
#define SMEM_LSTM (SMEM_TOT * 4)              // 232448 B (= max opt-in)

__global__ void __launch_bounds__(256, 1) lstm_persistent(float* __restrict__ out) {
    const int bid = blockIdx.x;
    const int dir = bid >> 6;
    const int j0  = (bid & 63) * 16;
    const uint32_t* Wtf = &g_Wtf[dir][0];

    extern __shared__ uint32_t smem[];
    const uint32_t sbase = (uint32_t)__cvta_generic_to_shared(smem);

    const int tid   = threadIdx.x;
    const int warp  = tid >> 5;
    const int lane  = tid & 31;
    const int warpM = warp & 1;
    const int warpN = (warp >> 1) & 1;
    const int kgrp  = warp >> 2;
    const int m0    = warpM * 32;
    const int nbase = warpN * 32;

    // ---- resident W (K 0..511), row = output col c, stride 516 ----
    for (int i = tid; i < 64 * 128; i += 256) {
        int c = i >> 7, kq = (i & 127) * 4;
        int gate = (c >> 3) & 3, j = j0 + ((c >> 5) << 3) + (c & 7);
        uint4 v = *(const uint4*)&Wtf[(size_t)(gate * HID + j) * HID + kq];
        uint32_t* d = smem + c * 516 + kq;
        d[0] = v.x; d[1] = v.y; d[2] = v.z; d[3] = v.w;
    }

    // ---- producer precompute: 6 granules/thread per ring slot ----
    uint32_t sRel[6]; uint32_t ghOff[4]; const uint32_t* gW[2];
#pragma unroll
    for (int q = 0; q < 6; q++) {
        int g = tid + (q & 1) * 256;          // 0..511 within part
        int part = q >> 1;                    // 0 hL, 1 hH, 2 W
        int r = g >> 3, sg = g & 7;
        sRel[q] = (uint32_t)(part * 2304 + r * 36 + sg * 4) * 4u;
        if (part < 2) {
            ghOff[q] = (uint32_t)(r * HID + part * 512 + sg * 4);
        } else {
            int gate = (r >> 3) & 3, j = j0 + ((r >> 5) << 3) + (r & 7);
            gW[q - 4] = Wtf + (size_t)(gate * HID + j) * HID + 512 + sg * 4;
        }
    }
    // xpre prefetch granules: 4 per thread
    uint32_t sxA[4]; uint32_t gxOff[4];
#pragma unroll
    for (int q = 0; q < 4; q++) {
        int i = tid + q * 256;                // 0..1023
        int b = i >> 4, seg = i & 15;
        int gate = seg >> 2, qq = seg & 3;
        sxA[q]   = sbase + (uint32_t)(XP_OFF + b * 68 + gate * 16 + qq * 4) * 4u;
        gxOff[q] = (uint32_t)(b * G4 + gate * HID + j0 + qq * 4);
    }

    // ---- ldmatrix lane-address components ----
    const int aoff0 = (m0 + ((lane >> 3) & 1) * 8 + (lane & 7)) * 36 + ((lane >> 4) << 2);
    const int aoff1 = aoff0 + 16 * 36;
    const int crow  = nbase + (lane >> 3) * 8 + (lane & 7);
    const int boffR = crow * 516;             // resident W
    const int boffS = 4608 + crow * 36;       // streamed W (slot-relative)

    float acc[2][4][4];
    float creg[8] = {0.f, 0.f, 0.f, 0.f, 0.f, 0.f, 0.f, 0.f};
    float hreg[8];

    __syncthreads();   // resident W visible

    // xpre prefetch for t = 0
    {
        const float* xg = &g_Xpre[dir][dir ? (TT - 1) : 0][0][0];
#pragma unroll
        for (int q = 0; q < 4; q++) CP_CG(sxA[q], xg + gxOff[q]);
        CP_COMMIT();
    }

    for (int t = 0; t < TT; t++) {
        const uint32_t* hin  = &g_htf[t & 1][dir][0][0];
        uint32_t*       hout = &g_htf[(t & 1) ^ 1][dir][0][0];

#pragma unroll
        for (int mf = 0; mf < 2; mf++)
#pragma unroll
            for (int nf = 0; nf < 4; nf++)
#pragma unroll
                for (int e = 0; e < 4; e++) acc[mf][nf][e] = 0.0f;

        // prologue: chunks 0..2 into slots 0..2
#pragma unroll
        for (int s = 0; s < 3; s++) {
            uint32_t sb = sbase + (uint32_t)(RING_OFF + s * SLOT_U32) * 4u;
#pragma unroll
            for (int q = 0; q < 4; q++) CP_CG(sb + sRel[q], hin + ghOff[q] + s * 32);
#pragma unroll
            for (int q = 4; q < 6; q++) CP_CA(sb + sRel[q], gW[q - 4] + s * 32);
            CP_COMMIT();
        }

        // main: 16 K-chunk iterations (each warp-group does its half)
        for (int it = 0; it < 16; it++) {
            CP_WAIT2();
            __syncthreads();

            const int slot = it % 3;
            const uint32_t slotB = sbase + (uint32_t)(RING_OFF + slot * SLOT_U32) * 4u;
            const uint32_t aB = slotB + (uint32_t)(kgrp * 2304) * 4u;
#pragma unroll
            for (int kk = 0; kk < 32; kk += 8) {
                uint4 A0 = ldsm4(aB + (uint32_t)(aoff0 + kk) * 4u);
                uint4 A1 = ldsm4(aB + (uint32_t)(aoff1 + kk) * 4u);
                uint4 B0, B1;
                if (kgrp == 0) {
                    uint32_t w = sbase + (uint32_t)(boffR + it * 32 + kk) * 4u;
                    B0 = ldsm4(w); B1 = ldsm4(w + 16u);
                } else {
                    uint32_t w = slotB + (uint32_t)(boffS + kk) * 4u;
                    B0 = ldsm4(w); B1 = ldsm4(w + 16u);
                }
                mma_tf32(acc[0][0], A0.x, A0.y, A0.z, A0.w, B0.x, B1.x);
                mma_tf32(acc[0][1], A0.x, A0.y, A0.z, A0.w, B0.y, B1.y);
                mma_tf32(acc[0][2], A0.x, A0.y, A0.z, A0.w, B0.z, B1.z);
                mma_tf32(acc[0][3], A0.x, A0.y, A0.z, A0.w, B0.w, B1.w);
                mma_tf32(acc[1][0], A1.x, A1.y, A1.z, A1.w, B0.x, B1.x);
                mma_tf32(acc[1][1], A1.x, A1.y, A1.z, A1.w, B0.y, B1.y);
                mma_tf32(acc[1][2], A1.x, A1.y, A1.z, A1.w, B0.z, B1.z);
                mma_tf32(acc[1][3], A1.x, A1.y, A1.z, A1.w, B0.w, B1.w);
            }

            __syncthreads();   // all warps done with this slot before refill
            if (it < 13) {
                int ch = it + 3;
                uint32_t sb = sbase + (uint32_t)(RING_OFF + slot * SLOT_U32) * 4u;
#pragma unroll
                for (int q = 0; q < 4; q++) CP_CG(sb + sRel[q], hin + ghOff[q] + ch * 32);
#pragma unroll
                for (int q = 4; q < 6; q++) CP_CA(sb + sRel[q], gW[q - 4] + ch * 32);
            }
            CP_COMMIT();
        }

        // ---- K-split reduction (ring region is free now) ----
        if (kgrp == 1) {
            float* dst = (float*)(smem + RED_OFF + (tid - 128) * 36);
            const float* af = &acc[0][0][0];
#pragma unroll
            for (int k = 0; k < 32; k++) dst[k] = af[k];
        }
        __syncthreads();

        // ---- fused LSTM epilogue (low warps) ----
        if (kgrp == 0) {
            const float* red = (const float*)(smem + RED_OFF + tid * 36);
            float* af = &acc[0][0][0];
#pragma unroll
            for (int k = 0; k < 32; k++) af[k] += red[k];

            const float* xs = (const float*)(smem + XP_OFF);
#pragma unroll
            for (int mf = 0; mf < 2; mf++) {
#pragma unroll
                for (int e = 0; e < 4; e++) {
                    int b  = m0 + mf * 16 + (lane >> 2) + ((e >> 1) << 3);
                    int jl = warpN * 8 + (lane & 3) * 2 + (e & 1);
                    int j  = j0 + jl;
                    float vi = acc[mf][0][e] + xs[b * 68 + jl];
                    float vf = acc[mf][1][e] + xs[b * 68 + 16 + jl];
                    float vg = acc[mf][2][e] + xs[b * 68 + 32 + jl];
                    float vo = acc[mf][3][e] + xs[b * 68 + 48 + jl];
                    int ci = mf * 4 + e;
                    float cn = sigf(vf) * creg[ci] + sigf(vi) * tanhf(vg);
                    float hn = sigf(vo) * tanhf(cn);
                    creg[ci] = cn;
                    hreg[ci] = hn;
                    hout[(size_t)b * HID + j] = f2tf32(hn);
                }
            }
        }

        // ---- step barrier (h visible), out-stores + xpre(t+1) off critical path
        __syncthreads();
        if (tid == 0) {
            __threadfence();
            atomicAdd(&g_bar[dir], 1u);
        }
        if (kgrp == 0) {
#pragma unroll
            for (int mf = 0; mf < 2; mf++)
#pragma unroll
                for (int e = 0; e < 4; e++) {
                    int b  = m0 + mf * 16 + (lane >> 2) + ((e >> 1) << 3);
                    int j  = j0 + warpN * 8 + (lane & 3) * 2 + (e & 1);
                    out[((size_t)b * TT + t) * (2 * HID) + dir * HID + j] = hreg[mf * 4 + e];
                }
        }
        if (t + 1 < TT) {
            const float* xg = &g_Xpre[dir][dir ? (TT - 2 - t) : (t + 1)][0][0];
#pragma unroll
            for (int q = 0; q < 4; q++) CP_CG(sxA[q], xg + gxOff[q]);
        }
        CP_COMMIT();
        if (tid == 0) {
            unsigned target = 64u * (unsigned)(t + 1);
            volatile unsigned* p = &g_bar[dir];
            while (*p < target) {}
            __threadfence();
        }
        __syncthreads();
    }

    // final cell state for final_fc
    if (kgrp == 0) {
#pragma unroll
        for (int mf = 0; mf < 2; mf++)
#pragma unroll
            for (int e = 0; e < 4; e++) {
                int b = m0 + mf * 16 + (lane >> 2) + ((e >> 1) << 3);
                int j = j0 + warpN * 8 + (lane & 3) * 2 + (e & 1);
                g_c[dir][b][j] = creg[mf * 4 + e];
            }
    }
}

// ---------------- final FCs: tanh(concat @ W^T + b) ----------------
__global__ void __launch_bounds__(256) final_fc(
    const float* __restrict__ fhW, const float* __restrict__ fhb,
    const float* __restrict__ fcW, const float* __restrict__ fcb,
    float* __restrict__ out) {
    const int which = blockIdx.y;
    const int n0 = blockIdx.x * 64;
    const float* W  = which ? fcW : fhW;
    const float* bb = which ? fcb : fhb;

    __shared__ float sA[64][33];
    __shared__ float sB[64][33];

    const int tid = threadIdx.x;
    const int rb = (tid >> 4) * 4;
    const int cb = (tid & 15) * 4;
    float acc[4][4] = {};

    for (int k0 = 0; k0 < 2 * HID; k0 += 32) {
        for (int i = tid; i < 512; i += 256) {
            int r = i >> 3, c = (i & 7) * 4;
            float4 v;
            if (which == 0) {
                v = *(const float4*)&out[((size_t)r * TT + (TT - 1)) * (2 * HID) + k0 + c];
            } else {
                int dir = k0 >> 10, kk0 = k0 & (HID - 1);
                v = *(const float4*)&g_c[dir][r][kk0 + c];
            }
            sA[r][c] = v.x; sA[r][c + 1] = v.y; sA[r][c + 2] = v.z; sA[r][c + 3] = v.w;
        }
        for (int i = tid; i < 512; i += 256) {
            int r = i >> 3, c = (i & 7) * 4;
            float4 v = *(const float4*)&W[(size_t)(n0 + r) * (2 * HID) + k0 + c];
            sB[r][c] = v.x; sB[r][c + 1] = v.y; sB[r][c + 2] = v.z; sB[r][c + 3] = v.w;
        }
        __syncthreads();
#pragma unroll
        for (int k = 0; k < 32; k++)
#pragma unroll
            for (int i = 0; i < 4; i++)
#pragma unroll
                for (int j = 0; j < 4; j++)
                    acc[i][j] += sA[rb + i][k] * sB[cb + j][k];
        __syncthreads();
    }

    size_t base = (size_t)BATCH * TT * 2 * HID + (size_t)which * BATCH * DDEC;
#pragma unroll
    for (int i = 0; i < 4; i++)
#pragma unroll
        for (int j = 0; j < 4; j++) {
            int n = n0 + cb + j;
            out[base + (size_t)(rb + i) * DDEC + n] = tanhf(acc[i][j] + bb[n]);
        }
}

// ---------------- entry ----------------
extern "C" void kernel_launch(void* const* d_in, const int* in_sizes, int n_in,
                              void* d_out, int out_size) {
    const float* X     = (const float*)d_in[0];
    const float* Wih_f = (const float*)d_in[1];
    const float* Whh_f = (const float*)d_in[2];
    const float* bih_f = (const float*)d_in[3];
    const float* bhh_f = (const float*)d_in[4];
    const float* Wih_b = (const float*)d_in[5];
    const float* Whh_b = (const float*)d_in[6];
    const float* bih_b = (const float*)d_in[7];
    const float* bhh_b = (const float*)d_in[8];
    const float* fc_W  = (const float*)d_in[9];
    const float* fc_b  = (const float*)d_in[10];
    const float* fh_W  = (const float*)d_in[11];
    const float* fh_b  = (const float*)d_in[12];
    float* out = (float*)d_out;

    static bool attr_set = false;
    if (!attr_set) {
        cudaFuncSetAttribute(lstm_persistent, cudaFuncAttributeMaxDynamicSharedMemorySize,
                             SMEM_LSTM);
        attr_set = true;
    }

    init_states<<<512, 256>>>();
    cvt_weights<<<dim3(G4 * HID / 1024, 2), 256>>>(Whh_f, Whh_b);
    gemm_xpre<<<dim3(64, 512, 2), 128>>>(X, Wih_f, Wih_b, bih_f, bhh_f, bih_b, bhh_b);
    lstm_persistent<<<128, 256, SMEM_LSTM>>>(out);
    final_fc<<<dim3(16, 2), 256>>>(fh_W, fh_b, fc_W, fc_b, out);
}

// round 11
// speedup vs baseline: 4.8245x; 1.1172x over previous
#include <cuda_runtime.h>
#include <cstdint>

#define BATCH 64
#define TT    512
#define DIN   512
#define HID   1024
#define G4    4096
#define DDEC  1024

// ---------------- device scratch (static, allocation-free) ----------------
__device__ float    g_Xpre[2][TT][BATCH][G4];        // 1 GiB
__device__ uint32_t g_htf[2][2][BATCH][HID];         // h as tf32 bits, ping-pong
__device__ float    g_c[2][BATCH][HID];              // final cell state
__device__ uint32_t g_Wtf[2][G4 * HID];              // W_hh as tf32 bits (32 MB)
__device__ uint32_t g_Wihtf[2][G4 * DIN];            // W_ih as tf32 bits (16 MB)
__device__ uint32_t g_Xtf[BATCH * TT * DIN];         // X as tf32 bits (64 MB)
__device__ unsigned g_bar[2];                        // per-direction step barrier

// ---------------- helpers ----------------
__device__ __forceinline__ uint32_t f2tf32(float x) {
    uint32_t r;
    asm("cvt.rna.tf32.f32 %0, %1;" : "=r"(r) : "f"(x));
    return r;
}

__device__ __forceinline__ void mma_tf32(float* c,
                                         uint32_t a0, uint32_t a1, uint32_t a2, uint32_t a3,
                                         uint32_t b0, uint32_t b1) {
    asm volatile(
        "mma.sync.aligned.m16n8k8.row.col.f32.tf32.tf32.f32 "
        "{%0,%1,%2,%3}, {%4,%5,%6,%7}, {%8,%9}, {%0,%1,%2,%3};"
        : "+f"(c[0]), "+f"(c[1]), "+f"(c[2]), "+f"(c[3])
        : "r"(a0), "r"(a1), "r"(a2), "r"(a3), "r"(b0), "r"(b1));
}

__device__ __forceinline__ uint4 ldsm4(uint32_t a) {
    uint4 r;
    asm volatile("ldmatrix.sync.aligned.m8n8.x4.shared.b16 {%0,%1,%2,%3}, [%4];"
                 : "=r"(r.x), "=r"(r.y), "=r"(r.z), "=r"(r.w) : "r"(a));
    return r;
}

__device__ __forceinline__ float sigf(float x) { return 1.0f / (1.0f + expf(-x)); }

#define CP_CG(sa, ga)  asm volatile("cp.async.cg.shared.global [%0], [%1], 16;\n" :: "r"(sa), "l"(ga))
#define CP_CA(sa, ga)  asm volatile("cp.async.ca.shared.global [%0], [%1], 16;\n" :: "r"(sa), "l"(ga))
#define CP_COMMIT()    asm volatile("cp.async.commit_group;\n" ::)
#define CP_WAIT2()     asm volatile("cp.async.wait_group 2;\n" ::)

// ---------------- init ----------------
__global__ void init_states() {
    int i = blockIdx.x * blockDim.x + threadIdx.x;   // 0 .. 131071
    ((uint32_t*)g_htf)[i] = 0u;                      // zeroes g_htf[0][*][*][*]
    if (i < 2) g_bar[i] = 0u;
}

// ---------------- one-time converts to tf32 bits ----------------
__global__ void __launch_bounds__(256) cvt_whh(
    const float* __restrict__ Wf, const float* __restrict__ Wb) {
    const int dir = blockIdx.y;
    const float* src = dir ? Wb : Wf;
    size_t i = ((size_t)blockIdx.x * 256 + threadIdx.x) * 4;
    float4 v = *(const float4*)(src + i);
    uint32_t* d = &g_Wtf[dir][i];
    d[0] = f2tf32(v.x); d[1] = f2tf32(v.y);
    d[2] = f2tf32(v.z); d[3] = f2tf32(v.w);
}

__global__ void __launch_bounds__(256) cvt_wih(
    const float* __restrict__ Wf, const float* __restrict__ Wb) {
    const int dir = blockIdx.y;
    const float* src = dir ? Wb : Wf;
    size_t i = ((size_t)blockIdx.x * 256 + threadIdx.x) * 4;
    float4 v = *(const float4*)(src + i);
    uint32_t* d = &g_Wihtf[dir][i];
    d[0] = f2tf32(v.x); d[1] = f2tf32(v.y);
    d[2] = f2tf32(v.z); d[3] = f2tf32(v.w);
}

__global__ void __launch_bounds__(256) cvt_x(const float* __restrict__ X) {
    size_t i = ((size_t)blockIdx.x * 256 + threadIdx.x) * 4;
    float4 v = *(const float4*)(X + i);
    uint32_t* d = &g_Xtf[i];
    d[0] = f2tf32(v.x); d[1] = f2tf32(v.y);
    d[2] = f2tf32(v.z); d[3] = f2tf32(v.w);
}

// ---------------- big GEMM v2: Xpre = X @ W_ih^T + (b_ih + b_hh) ----------------
// grid (32 nt, 512 t, 2 dir), 256 threads = 8 warps (2M x 4N), tile 64x128, K=512.
// Preconverted tf32 inputs, 3-stage cp.async ring, ldmatrix.x4 feeds.
#define GX_SLOT_U32 6912                    // A 64x36 + B 128x36
#define GX_SMEM     (3 * GX_SLOT_U32 * 4)   // 82944 B

__global__ void __launch_bounds__(256, 2) gemm_xpre2(
    const float* __restrict__ bih_f, const float* __restrict__ bhh_f,
    const float* __restrict__ bih_b, const float* __restrict__ bhh_b) {
    const int nt  = blockIdx.x;
    const int t   = blockIdx.y;
    const int dir = blockIdx.z;
    const int n0  = nt * 128;
    const float* bi = dir ? bih_b : bih_f;
    const float* bh = dir ? bhh_b : bhh_f;
    const uint32_t* Xtf = g_Xtf + (size_t)t * DIN;
    const uint32_t* Wih = &g_Wihtf[dir][0];

    extern __shared__ uint32_t smem[];
    const uint32_t sbase = (uint32_t)__cvta_generic_to_shared(smem);

    const int tid   = threadIdx.x;
    const int warp  = tid >> 5;
    const int lane  = tid & 31;
    const int warpM = warp & 1;
    const int warpN = warp >> 1;
    const int m0    = warpM * 32;
    const int nbase = warpN * 32;

    // producer granules: 6 x 16B per thread per chunk
    uint32_t sRel[6];
    const uint32_t* gp[6];
#pragma unroll
    for (int q = 0; q < 6; q++) {
        int i = tid + q * 256;
        if (i < 512) {                       // A: 64 rows (batch) x 32 k
            int r = i >> 3, sg = i & 7;
            sRel[q] = (uint32_t)(r * 36 + sg * 4) * 4u;
            gp[q]   = Xtf + (size_t)r * TT * DIN + sg * 4;
        } else {                             // B: 128 rows (out cols) x 32 k
            int j = i - 512;
            int r = j >> 3, sg = j & 7;
            sRel[q] = (uint32_t)(2304 + r * 36 + sg * 4) * 4u;
            gp[q]   = Wih + (size_t)(n0 + r) * DIN + sg * 4;
        }
    }

    // bias per thread (8 distinct output cols)
    float bsum[4][2];
#pragma unroll
    for (int nf = 0; nf < 4; nf++)
#pragma unroll
        for (int e1 = 0; e1 < 2; e1++) {
            int n = n0 + nbase + nf * 8 + (lane & 3) * 2 + e1;
            bsum[nf][e1] = bi[n] + bh[n];
        }

    float acc[2][4][4];
#pragma unroll
    for (int mf = 0; mf < 2; mf++)
#pragma unroll
        for (int nf = 0; nf < 4; nf++)
#pragma unroll
            for (int e = 0; e < 4; e++) acc[mf][nf][e] = 0.0f;

    // prologue: 3 chunks
#pragma unroll
    for (int s = 0; s < 3; s++) {
        uint32_t sb = sbase + (uint32_t)(s * GX_SLOT_U32) * 4u;
#pragma unroll
        for (int q = 0; q < 6; q++) CP_CG(sb + sRel[q], gp[q] + s * 32);
        CP_COMMIT();
    }

    const int aoff0 = (m0 + ((lane >> 3) & 1) * 8 + (lane & 7)) * 36 + ((lane >> 4) << 2);
    const int boff  = 2304 + (nbase + (lane >> 3) * 8 + (lane & 7)) * 36;

    for (int it = 0; it < 16; it++) {
        CP_WAIT2();
        __syncthreads();
        const uint32_t slotB = sbase + (uint32_t)((it % 3) * GX_SLOT_U32) * 4u;
#pragma unroll
        for (int kk = 0; kk < 32; kk += 8) {
            uint4 A0 = ldsm4(slotB + (uint32_t)(aoff0 + kk) * 4u);
            uint4 A1 = ldsm4(slotB + (uint32_t)(aoff0 + 16 * 36 + kk) * 4u);
            uint32_t w = slotB + (uint32_t)(boff + kk) * 4u;
            uint4 B0 = ldsm4(w);
            uint4 B1 = ldsm4(w + 16u);
            mma_tf32(acc[0][0], A0.x, A0.y, A0.z, A0.w, B0.x, B1.x);
            mma_tf32(acc[0][1], A0.x, A0.y, A0.z, A0.w, B0.y, B1.y);
            mma_tf32(acc[0][2], A0.x, A0.y, A0.z, A0.w, B0.z, B1.z);
            mma_tf32(acc[0][3], A0.x, A0.y, A0.z, A0.w, B0.w, B1.w);
            mma_tf32(acc[1][0], A1.x, A1.y, A1.z, A1.w, B0.x, B1.x);
            mma_tf32(acc[1][1], A1.x, A1.y, A1.z, A1.w, B0.y, B1.y);
            mma_tf32(acc[1][2], A1.x, A1.y, A1.z, A1.w, B0.z, B1.z);
            mma_tf32(acc[1][3], A1.x, A1.y, A1.z, A1.w, B0.w, B1.w);
        }
        __syncthreads();
        int ch = it + 3;
        if (ch < 16) {
            uint32_t sb = sbase + (uint32_t)((ch % 3) * GX_SLOT_U32) * 4u;
#pragma unroll
            for (int q = 0; q < 6; q++) CP_CG(sb + sRel[q], gp[q] + ch * 32);
        }
        CP_COMMIT();
    }

    // epilogue: add bias, write 64x128 f32
    float* dst = &g_Xpre[dir][t][0][0];
#pragma unroll
    for (int mf = 0; mf < 2; mf++)
#pragma unroll
        for (int nf = 0; nf < 4; nf++)
#pragma unroll
            for (int eh = 0; eh < 2; eh++) {
                int b = m0 + mf * 16 + (lane >> 2) + eh * 8;
                int n = n0 + nbase + nf * 8 + (lane & 3) * 2;
                float2 v;
                v.x = acc[mf][nf][eh * 2 + 0] + bsum[nf][0];
                v.y = acc[mf][nf][eh * 2 + 1] + bsum[nf][1];
                *(float2*)&dst[(size_t)b * G4 + n] = v;
            }
}

// ---------------- persistent LSTM v3 ----------------
// 128 blocks = 64 j-tiles x 2 dirs, 256 threads = 8 warps:
//   warpM = warp&1, warpN = (warp>>1)&1, kgrp = warp>>2 (K-split).
// v3: h staged in SMEM, coalesced STG.128 stores of h-out (pre-barrier) and
// out (post-arrive); everything else identical to the passing v2.
#define WRES_U32  (64 * 516)                 // 33024 u32
#define SLOT_U32  6912                        // hL + hH + W chunk
#define RING_OFF  WRES_U32                    // 33024
#define RED_OFF   RING_OFF                    // reduction overlays ring slot0 (h parts)
#define SH_OFF    (RING_OFF + 4608)           // h staging overlays ring slot0 (W part)
#define XP_OFF    (RING_OFF + 3 * SLOT_U32)   // 53760
#define SMEM_TOT  (XP_OFF + 64 * 68)          // 58112 u32
#define SMEM_LSTM (SMEM_TOT * 4)              // 232448 B

__global__ void __launch_bounds__(256, 1) lstm_persistent(float* __restrict__ out) {
    const int bid = blockIdx.x;
    const int dir = bid >> 6;
    const int j0  = (bid & 63) * 16;
    const uint32_t* Wtf = &g_Wtf[dir][0];

    extern __shared__ uint32_t smem[];
    const uint32_t sbase = (uint32_t)__cvta_generic_to_shared(smem);
    float* sHf = (float*)(smem + SH_OFF);     // [64][20] staged h

    const int tid   = threadIdx.x;
    const int warp  = tid >> 5;
    const int lane  = tid & 31;
    const int warpM = warp & 1;
    const int warpN = (warp >> 1) & 1;
    const int kgrp  = warp >> 2;
    const int m0    = warpM * 32;
    const int nbase = warpN * 32;

    // ---- resident W (K 0..511), row = output col c, stride 516 ----
    for (int i = tid; i < 64 * 128; i += 256) {
        int c = i >> 7, kq = (i & 127) * 4;
        int gate = (c >> 3) & 3, j = j0 + ((c >> 5) << 3) + (c & 7);
        uint4 v = *(const uint4*)&Wtf[(size_t)(gate * HID + j) * HID + kq];
        uint32_t* d = smem + c * 516 + kq;
        d[0] = v.x; d[1] = v.y; d[2] = v.z; d[3] = v.w;
    }

    // ---- producer precompute: 6 granules/thread per ring slot ----
    uint32_t sRel[6]; uint32_t ghOff[4]; const uint32_t* gW[2];
#pragma unroll
    for (int q = 0; q < 6; q++) {
        int g = tid + (q & 1) * 256;          // 0..511 within part
        int part = q >> 1;                    // 0 hL, 1 hH, 2 W
        int r = g >> 3, sg = g & 7;
        sRel[q] = (uint32_t)(part * 2304 + r * 36 + sg * 4) * 4u;
        if (part < 2) {
            ghOff[q] = (uint32_t)(r * HID + part * 512 + sg * 4);
        } else {
            int gate = (r >> 3) & 3, j = j0 + ((r >> 5) << 3) + (r & 7);
            gW[q - 4] = Wtf + (size_t)(gate * HID + j) * HID + 512 + sg * 4;
        }
    }
    // xpre prefetch granules: 4 per thread
    uint32_t sxA[4]; uint32_t gxOff[4];
#pragma unroll
    for (int q = 0; q < 4; q++) {
        int i = tid + q * 256;                // 0..1023
        int b = i >> 4, seg = i & 15;
        int gate = seg >> 2, qq = seg & 3;
        sxA[q]   = sbase + (uint32_t)(XP_OFF + b * 68 + gate * 16 + qq * 4) * 4u;
        gxOff[q] = (uint32_t)(b * G4 + gate * HID + j0 + qq * 4);
    }

    const int aoff0 = (m0 + ((lane >> 3) & 1) * 8 + (lane & 7)) * 36 + ((lane >> 4) << 2);
    const int aoff1 = aoff0 + 16 * 36;
    const int crow  = nbase + (lane >> 3) * 8 + (lane & 7);
    const int boffR = crow * 516;
    const int boffS = 4608 + crow * 36;

    float acc[2][4][4];
    float creg[8] = {0.f, 0.f, 0.f, 0.f, 0.f, 0.f, 0.f, 0.f};

    __syncthreads();   // resident W visible

    // xpre prefetch for t = 0
    {
        const float* xg = &g_Xpre[dir][dir ? (TT - 1) : 0][0][0];
#pragma unroll
        for (int q = 0; q < 4; q++) CP_CG(sxA[q], xg + gxOff[q]);
        CP_COMMIT();
    }

    for (int t = 0; t < TT; t++) {
        const uint32_t* hin  = &g_htf[t & 1][dir][0][0];
        uint32_t*       hout = &g_htf[(t & 1) ^ 1][dir][0][0];

#pragma unroll
        for (int mf = 0; mf < 2; mf++)
#pragma unroll
            for (int nf = 0; nf < 4; nf++)
#pragma unroll
                for (int e = 0; e < 4; e++) acc[mf][nf][e] = 0.0f;

        // prologue: chunks 0..2
#pragma unroll
        for (int s = 0; s < 3; s++) {
            uint32_t sb = sbase + (uint32_t)(RING_OFF + s * SLOT_U32) * 4u;
#pragma unroll
            for (int q = 0; q < 4; q++) CP_CG(sb + sRel[q], hin + ghOff[q] + s * 32);
#pragma unroll
            for (int q = 4; q < 6; q++) CP_CA(sb + sRel[q], gW[q - 4] + s * 32);
            CP_COMMIT();
        }

        // main: 16 K-chunk iterations
        for (int it = 0; it < 16; it++) {
            CP_WAIT2();
            __syncthreads();

            const int slot = it % 3;
            const uint32_t slotB = sbase + (uint32_t)(RING_OFF + slot * SLOT_U32) * 4u;
            const uint32_t aB = slotB + (uint32_t)(kgrp * 2304) * 4u;
#pragma unroll
            for (int kk = 0; kk < 32; kk += 8) {
                uint4 A0 = ldsm4(aB + (uint32_t)(aoff0 + kk) * 4u);
                uint4 A1 = ldsm4(aB + (uint32_t)(aoff1 + kk) * 4u);
                uint4 B0, B1;
                if (kgrp == 0) {
                    uint32_t w = sbase + (uint32_t)(boffR + it * 32 + kk) * 4u;
                    B0 = ldsm4(w); B1 = ldsm4(w + 16u);
                } else {
                    uint32_t w = slotB + (uint32_t)(boffS + kk) * 4u;
                    B0 = ldsm4(w); B1 = ldsm4(w + 16u);
                }
                mma_tf32(acc[0][0], A0.x, A0.y, A0.z, A0.w, B0.x, B1.x);
                mma_tf32(acc[0][1], A0.x, A0.y, A0.z, A0.w, B0.y, B1.y);
                mma_tf32(acc[0][2], A0.x, A0.y, A0.z, A0.w, B0.z, B1.z);
                mma_tf32(acc[0][3], A0.x, A0.y, A0.z, A0.w, B0.w, B1.w);
                mma_tf32(acc[1][0], A1.x, A1.y, A1.z, A1.w, B0.x, B1.x);
                mma_tf32(acc[1][1], A1.x, A1.y, A1.z, A1.w, B0.y, B1.y);
                mma_tf32(acc[1][2], A1.x, A1.y, A1.z, A1.w, B0.z, B1.z);
                mma_tf32(acc[1][3], A1.x, A1.y, A1.z, A1.w, B0.w, B1.w);
            }

            __syncthreads();   // all warps done with this slot before refill
            if (it < 13) {
                int ch = it + 3;
                uint32_t sb = sbase + (uint32_t)(RING_OFF + slot * SLOT_U32) * 4u;
#pragma unroll
                for (int q = 0; q < 4; q++) CP_CG(sb + sRel[q], hin + ghOff[q] + ch * 32);
#pragma unroll
                for (int q = 4; q < 6; q++) CP_CA(sb + sRel[q], gW[q - 4] + ch * 32);
            }
            CP_COMMIT();
        }

        // ---- K-split reduction (ring slot0 h-region is free now) ----
        if (kgrp == 1) {
            float* dst = (float*)(smem + RED_OFF + (tid - 128) * 36);
            const float* af = &acc[0][0][0];
#pragma unroll
            for (int k = 0; k < 32; k++) dst[k] = af[k];
        }
        __syncthreads();

        // ---- fused LSTM epilogue (low warps) -> stage h in SMEM ----
        if (kgrp == 0) {
            const float* red = (const float*)(smem + RED_OFF + tid * 36);
            float* af = &acc[0][0][0];
#pragma unroll
            for (int k = 0; k < 32; k++) af[k] += red[k];

            const float* xs = (const float*)(smem + XP_OFF);
#pragma unroll
            for (int mf = 0; mf < 2; mf++) {
#pragma unroll
                for (int e = 0; e < 4; e++) {
                    int b  = m0 + mf * 16 + (lane >> 2) + ((e >> 1) << 3);
                    int jl = warpN * 8 + (lane & 3) * 2 + (e & 1);
                    float vi = acc[mf][0][e] + xs[b * 68 + jl];
                    float vf = acc[mf][1][e] + xs[b * 68 + 16 + jl];
                    float vg = acc[mf][2][e] + xs[b * 68 + 32 + jl];
                    float vo = acc[mf][3][e] + xs[b * 68 + 48 + jl];
                    int ci = mf * 4 + e;
                    float cn = sigf(vf) * creg[ci] + sigf(vi) * tanhf(vg);
                    float hn = sigf(vo) * tanhf(cn);
                    creg[ci] = cn;
                    sHf[b * 20 + jl] = hn;
                }
            }
        }
        __syncthreads();

        // ---- coalesced h-out store (must precede barrier arrive) ----
        {
            int b = tid >> 2, q = tid & 3;
            float4 hv = *(const float4*)(sHf + b * 20 + q * 4);
            uint4 ht;
            ht.x = f2tf32(hv.x); ht.y = f2tf32(hv.y);
            ht.z = f2tf32(hv.z); ht.w = f2tf32(hv.w);
            *(uint4*)&hout[(size_t)b * HID + j0 + q * 4] = ht;
        }
        __syncthreads();

        if (tid == 0) {
            __threadfence();
            atomicAdd(&g_bar[dir], 1u);
        }
        // ---- out store + xpre(t+1) prefetch, off the barrier critical path ----
        {
            int b = tid >> 2, q = tid & 3;
            float4 hv = *(const float4*)(sHf + b * 20 + q * 4);
            *(float4*)&out[((size_t)b * TT + t) * (2 * HID) + dir * HID + j0 + q * 4] = hv;
        }
        if (t + 1 < TT) {
            const float* xg = &g_Xpre[dir][dir ? (TT - 2 - t) : (t + 1)][0][0];
#pragma unroll
            for (int q = 0; q < 4; q++) CP_CG(sxA[q], xg + gxOff[q]);
        }
        CP_COMMIT();
        if (tid == 0) {
            unsigned target = 64u * (unsigned)(t + 1);
            volatile unsigned* p = &g_bar[dir];
            while (*p < target) {}
            __threadfence();
        }
        __syncthreads();
    }

    // final cell state for final_fc
    if (kgrp == 0) {
#pragma unroll
        for (int mf = 0; mf < 2; mf++)
#pragma unroll
            for (int e = 0; e < 4; e++) {
                int b = m0 + mf * 16 + (lane >> 2) + ((e >> 1) << 3);
                int j = j0 + warpN * 8 + (lane & 3) * 2 + (e & 1);
                g_c[dir][b][j] = creg[mf * 4 + e];
            }
    }
}

// ---------------- final FCs: tanh(concat @ W^T + b) ----------------
__global__ void __launch_bounds__(256) final_fc(
    const float* __restrict__ fhW, const float* __restrict__ fhb,
    const float* __restrict__ fcW, const float* __restrict__ fcb,
    float* __restrict__ out) {
    const int which = blockIdx.y;
    const int n0 = blockIdx.x * 64;
    const float* W  = which ? fcW : fhW;
    const float* bb = which ? fcb : fhb;

    __shared__ float sA[64][33];
    __shared__ float sB[64][33];

    const int tid = threadIdx.x;
    const int rb = (tid >> 4) * 4;
    const int cb = (tid & 15) * 4;
    float acc[4][4] = {};

    for (int k0 = 0; k0 < 2 * HID; k0 += 32) {
        for (int i = tid; i < 512; i += 256) {
            int r = i >> 3, c = (i & 7) * 4;
            float4 v;
            if (which == 0) {
                v = *(const float4*)&out[((size_t)r * TT + (TT - 1)) * (2 * HID) + k0 + c];
            } else {
                int dir = k0 >> 10, kk0 = k0 & (HID - 1);
                v = *(const float4*)&g_c[dir][r][kk0 + c];
            }
            sA[r][c] = v.x; sA[r][c + 1] = v.y; sA[r][c + 2] = v.z; sA[r][c + 3] = v.w;
        }
        for (int i = tid; i < 512; i += 256) {
            int r = i >> 3, c = (i & 7) * 4;
            float4 v = *(const float4*)&W[(size_t)(n0 + r) * (2 * HID) + k0 + c];
            sB[r][c] = v.x; sB[r][c + 1] = v.y; sB[r][c + 2] = v.z; sB[r][c + 3] = v.w;
        }
        __syncthreads();
#pragma unroll
        for (int k = 0; k < 32; k++)
#pragma unroll
            for (int i = 0; i < 4; i++)
#pragma unroll
                for (int j = 0; j < 4; j++)
                    acc[i][j] += sA[rb + i][k] * sB[cb + j][k];
        __syncthreads();
    }

    size_t base = (size_t)BATCH * TT * 2 * HID + (size_t)which * BATCH * DDEC;
#pragma unroll
    for (int i = 0; i < 4; i++)
#pragma unroll
        for (int j = 0; j < 4; j++) {
            int n = n0 + cb + j;
            out[base + (size_t)(rb + i) * DDEC + n] = tanhf(acc[i][j] + bb[n]);
        }
}

// ---------------- entry ----------------
extern "C" void kernel_launch(void* const* d_in, const int* in_sizes, int n_in,
                              void* d_out, int out_size) {
    const float* X     = (const float*)d_in[0];
    const float* Wih_f = (const float*)d_in[1];
    const float* Whh_f = (const float*)d_in[2];
    const float* bih_f = (const float*)d_in[3];
    const float* bhh_f = (const float*)d_in[4];
    const float* Wih_b = (const float*)d_in[5];
    const float* Whh_b = (const float*)d_in[6];
    const float* bih_b = (const float*)d_in[7];
    const float* bhh_b = (const float*)d_in[8];
    const float* fc_W  = (const float*)d_in[9];
    const float* fc_b  = (const float*)d_in[10];
    const float* fh_W  = (const float*)d_in[11];
    const float* fh_b  = (const float*)d_in[12];
    float* out = (float*)d_out;

    static bool attr_set = false;
    if (!attr_set) {
        cudaFuncSetAttribute(lstm_persistent, cudaFuncAttributeMaxDynamicSharedMemorySize,
                             SMEM_LSTM);
        cudaFuncSetAttribute(gemm_xpre2, cudaFuncAttributeMaxDynamicSharedMemorySize,
                             GX_SMEM);
        attr_set = true;
    }

    init_states<<<512, 256>>>();
    cvt_whh<<<dim3(G4 * HID / 1024, 2), 256>>>(Whh_f, Whh_b);
    cvt_wih<<<dim3(G4 * DIN / 1024, 2), 256>>>(Wih_f, Wih_b);
    cvt_x<<<BATCH * TT * DIN / 1024, 256>>>(X);
    gemm_xpre2<<<dim3(32, 512, 2), 256, GX_SMEM>>>(bih_f, bhh_f, bih_b, bhh_b);
    lstm_persistent<<<128, 256, SMEM_LSTM>>>(out);
    final_fc<<<dim3(16, 2), 256>>>(fh_W, fh_b, fc_W, fc_b, out);
}